// round 1
// baseline (speedup 1.0000x reference)
#include <cuda_runtime.h>
#include <math.h>

#define BATCH  8
#define CHN    128
#define HEADS  8
#define HC     16
#define NPIX   65536
#define EPS    1e-5f

#define BS     68     // pixel-buffer row stride (floats): 272B, 16B-aligned rows
#define WS     129    // kernel-A weight row stride (odd -> conflict-free scalar LDS)
#define MS     132    // kernel-C weight row stride: 528B, 16B-aligned rows
#define CHUNK  64     // pixels per smem chunk
#define NCHUNK 16     // chunks per block -> 1024 pixels/block

typedef unsigned long long ull;

// -------- persistent device scratch (no allocations allowed) --------
__device__ float g_kv[BATCH * HEADS * HC * HC];   // kv accumulators
__device__ float g_M1t[BATCH * CHN * CHN];        // fused matrix o1*(A+I), stored [c][o]
__device__ float g_o2t[CHN * CHN];                // o2_w transposed [c][o]

// -------- packed f32x2 helpers (FFMA2: 2x fp32 FMA throughput on sm_103a) ----
static __device__ __forceinline__ ull fma2(ull a, ull b, ull c) {
    ull d;
    asm("fma.rn.f32x2 %0, %1, %2, %3;" : "=l"(d) : "l"(a), "l"(b), "l"(c));
    return d;
}
static __device__ __forceinline__ ull pack2(float lo, float hi) {
    ull d;
    asm("mov.b64 %0, {%1, %2};" : "=l"(d) : "f"(lo), "f"(hi));
    return d;
}
static __device__ __forceinline__ float2 unpack2(ull v) {
    float2 r;
    asm("mov.b64 {%0, %1}, %2;" : "=f"(r.x), "=f"(r.y) : "l"(v));
    return r;
}
static __device__ __forceinline__ float gelu_exact(float v) {
    return v * normcdff(v);   // exact gelu: x * Phi(x)
}

// ============================================================================
// Kernel 0: zero the kv accumulators
// ============================================================================
__global__ void zero_kv_kernel() {
    int i = blockIdx.x * blockDim.x + threadIdx.x;
    if (i < BATCH * HEADS * HC * HC) g_kv[i] = 0.f;
}

// ============================================================================
// Kernel A: k,v = W_kv @ x per pixel; LayerNorm(16) each head; accumulate
// kv[b,h,16,16] += k_ln^T v_ln  (division by N deferred to kernel B).
//
// qkv reshape in the reference is (heads, 3*hc): output channel of qkv_w for
// head h is  q: h*48+d,  k: h*48+16+d,  v: h*48+32+d.
// Local row layout o in [0,256): head = o>>5, k rows o&31 in [0,16),
// v rows in [16,32)  ->  global qkv_w row = (o>>5)*48 + 16 + (o&31).
// ============================================================================
__global__ void __launch_bounds__(256, 1) kv_accum_kernel(
    const float* __restrict__ x, const float* __restrict__ qkv_w,
    const float* __restrict__ klw, const float* __restrict__ klb,
    const float* __restrict__ vlw, const float* __restrict__ vlb)
{
    extern __shared__ float sm[];
    float* Wsm = sm;                  // [256][WS]
    float* buf = sm + 256 * WS;       // [256][BS]  (rows 0..127 double as x tile)
    float* lw  = buf + 256 * BS;      // [256] LN weight per local row
    float* lb  = lw + 256;            // [256] LN bias per local row

    const int tid = threadIdx.x;
    const int b   = blockIdx.y;
    const int n0  = blockIdx.x * (CHUNK * NCHUNK);

    // load k/v weights (coalesced global, stride-1 smem writes)
    for (int idx = tid; idx < 256 * CHN; idx += 256) {
        int o = idx >> 7, c = idx & 127;
        int row = (o >> 5) * 48 + 16 + (o & 31);
        Wsm[o * WS + c] = qkv_w[row * CHN + c];
    }
    {   // LN params, mapped onto local row index
        int o = tid, h = o >> 5, d = o & 15;
        if (o & 16) { lw[o] = vlw[h * HC + d]; lb[o] = vlb[h * HC + d]; }
        else        { lw[o] = klw[h * HC + d]; lb[o] = klb[h * HC + d]; }
    }

    const int to = tid >> 3, tp = tid & 7;
    const int p0 = tp * 8;
    const int warp = tid >> 5, lane = tid & 31;
    const int dd = lane >> 1, e0 = (lane & 1) * 8;   // lane owns (dd, e0..e0+7)

    ull kvacc[8];
    #pragma unroll
    for (int t = 0; t < 8; t++) kvacc[t] = 0ull;

    for (int ch = 0; ch < NCHUNK; ch++) {
        const int nb = n0 + ch * CHUNK;
        __syncthreads();   // orders weight load / previous chunk before x reload

        // x tile: rows 0..127 of buf
        {
            int c = tid >> 1;
            int half = (tid & 1) * 32;
            const float4* gx = reinterpret_cast<const float4*>(
                x + ((size_t)b * CHN + c) * NPIX + nb + half);
            float4* dst = reinterpret_cast<float4*>(&buf[c * BS + half]);
            #pragma unroll
            for (int q = 0; q < 8; q++) dst[q] = gx[q];
        }
        __syncthreads();

        // GEMM: 256 outputs x 64 pixels x 128 K, 8x8 micro-tile, f32x2 packed
        ull acc[8][4];
        #pragma unroll
        for (int i = 0; i < 8; i++)
            #pragma unroll
            for (int j = 0; j < 4; j++) acc[i][j] = 0ull;

        const float* Wr = &Wsm[(to * 8) * WS];
        #pragma unroll 4
        for (int k = 0; k < CHN; k++) {
            ulonglong2 xa = *reinterpret_cast<const ulonglong2*>(&buf[k * BS + p0]);
            ulonglong2 xb = *reinterpret_cast<const ulonglong2*>(&buf[k * BS + p0 + 4]);
            #pragma unroll
            for (int i = 0; i < 8; i++) {
                float w = Wr[i * WS + k];
                ull wp = pack2(w, w);
                acc[i][0] = fma2(wp, xa.x, acc[i][0]);
                acc[i][1] = fma2(wp, xa.y, acc[i][1]);
                acc[i][2] = fma2(wp, xb.x, acc[i][2]);
                acc[i][3] = fma2(wp, xb.y, acc[i][3]);
            }
        }
        __syncthreads();   // all x reads done; buf rows 0..127 now dead

        // store raw k,v into buf[256][BS]
        #pragma unroll
        for (int i = 0; i < 8; i++) {
            ull* dst = reinterpret_cast<ull*>(&buf[(to * 8 + i) * BS + p0]);
            dst[0] = acc[i][0]; dst[1] = acc[i][1];
            dst[2] = acc[i][2]; dst[3] = acc[i][3];
        }
        __syncthreads();

        // LayerNorm: 64 pixels x 8 heads x {k,v}; torch variant:
        // unbiased std (ddof=1), eps added to std.
        #pragma unroll
        for (int rep = 0; rep < 2; rep++) {
            int task = tid + rep * 256;          // 512 tasks
            int p  = task & 63;
            int hh = task >> 6;
            #pragma unroll
            for (int part = 0; part < 2; part++) {
                int rbase = hh * 32 + part * 16;
                float t[16]; float s = 0.f;
                #pragma unroll
                for (int d = 0; d < 16; d++) { t[d] = buf[(rbase + d) * BS + p]; s += t[d]; }
                float m = s * (1.f / 16.f);
                float var = 0.f;
                #pragma unroll
                for (int d = 0; d < 16; d++) { float dv = t[d] - m; var += dv * dv; }
                float inv = 1.f / (sqrtf(var * (1.f / 15.f)) + EPS);
                #pragma unroll
                for (int d = 0; d < 16; d++)
                    buf[(rbase + d) * BS + p] =
                        lw[rbase + d] * ((t[d] - m) * inv) + lb[rbase + d];
            }
        }
        __syncthreads();

        // kv outer product: warp w = head w; pairs over pixels (f32x2)
        const float* kr = &buf[(warp * 32 + dd) * BS];
        #pragma unroll 4
        for (int p = 0; p < CHUNK; p += 2) {
            ull k2 = *reinterpret_cast<const ull*>(&kr[p]);
            #pragma unroll
            for (int t = 0; t < 8; t++) {
                ull v2 = *reinterpret_cast<const ull*>(
                    &buf[(warp * 32 + 16 + e0 + t) * BS + p]);
                kvacc[t] = fma2(k2, v2, kvacc[t]);
            }
        }
    }

    #pragma unroll
    for (int t = 0; t < 8; t++) {
        float2 v = unpack2(kvacc[t]);
        atomicAdd(&g_kv[((b * HEADS + warp) * HC + dd) * HC + e0 + t], v.x + v.y);
    }
}

// ============================================================================
// Kernel B: fold attention into a per-batch 128x128 matrix.
//   A[b][h*16+e][c] = sum_d qkv_w[h*48+d][c] * kv[b,h,d,e] / N
//   M1[b] = o1_w @ (A[b] + I),  stored transposed [c][o].
// Also transposes o2_w once.
// ============================================================================
__global__ void build_mats_kernel(const float* __restrict__ qkv_w,
                                  const float* __restrict__ o1_w,
                                  const float* __restrict__ o2_w)
{
    extern __shared__ float sm[];
    float* kvs = sm;            // [HEADS*HC*HC] = 2048
    float* As  = sm + 2048;     // [128][129]
    const int tid = threadIdx.x;
    const int b   = blockIdx.x;

    for (int i = tid; i < HEADS * HC * HC; i += 256)
        kvs[i] = g_kv[b * HEADS * HC * HC + i] * (1.f / NPIX);
    __syncthreads();

    for (int idx = tid; idx < CHN * CHN; idx += 256) {
        int j = idx >> 7, c = idx & 127;
        int h = j >> 4,  e = j & 15;
        float s = 0.f;
        #pragma unroll
        for (int d = 0; d < HC; d++)
            s += qkv_w[(h * 48 + d) * CHN + c] * kvs[(h * HC + d) * HC + e];
        As[j * 129 + c] = s;
    }
    __syncthreads();

    for (int idx = tid; idx < CHN * CHN; idx += 256) {
        int c = idx >> 7, o = idx & 127;
        float s = o1_w[o * CHN + c];            // identity term
        for (int j = 0; j < CHN; j++)
            s += o1_w[o * CHN + j] * As[j * 129 + c];
        g_M1t[((size_t)b * CHN + c) * CHN + o] = s;
    }
    if (b == 0) {
        for (int idx = tid; idx < CHN * CHN; idx += 256) {
            int c = idx >> 7, o = idx & 127;
            g_o2t[c * CHN + o] = o2_w[o * CHN + c];
        }
    }
}

// ============================================================================
// Kernel C: out = gelu( o2_w @ gelu( M1[b] @ x ) + x )
// Two 128x128xP GEMMs per pixel tile, 4x8 micro-tile, f32x2 packed.
// ============================================================================
__global__ void __launch_bounds__(256, 1) mlp_kernel(
    const float* __restrict__ x, float* __restrict__ out)
{
    extern __shared__ float sm[];
    float* M1s = sm;                   // [128][MS]
    float* O2s = M1s + CHN * MS;       // [128][MS]
    float* xs  = O2s + CHN * MS;       // [128][BS]
    float* u1  = xs  + CHN * BS;       // [128][BS]

    const int tid = threadIdx.x;
    const int b   = blockIdx.y;
    const int n0  = blockIdx.x * (CHUNK * NCHUNK);

    for (int idx = tid; idx < CHN * CHN; idx += 256) {
        int k = idx >> 7, o = idx & 127;
        M1s[k * MS + o] = g_M1t[((size_t)b * CHN + k) * CHN + o];
        O2s[k * MS + o] = g_o2t[k * CHN + o];
    }

    const int to = tid >> 3, tp = tid & 7;
    const int o0 = to * 4, p0 = tp * 8;

    for (int ch = 0; ch < NCHUNK; ch++) {
        const int nb = n0 + ch * CHUNK;
        __syncthreads();

        {   // x tile
            int c = tid >> 1;
            int half = (tid & 1) * 32;
            const float4* gx = reinterpret_cast<const float4*>(
                x + ((size_t)b * CHN + c) * NPIX + nb + half);
            float4* dst = reinterpret_cast<float4*>(&xs[c * BS + half]);
            #pragma unroll
            for (int q = 0; q < 8; q++) dst[q] = gx[q];
        }
        __syncthreads();

        // GEMM1: u1 = M1 @ x
        ull a1[4][4];
        #pragma unroll
        for (int i = 0; i < 4; i++)
            #pragma unroll
            for (int j = 0; j < 4; j++) a1[i][j] = 0ull;

        #pragma unroll 4
        for (int k = 0; k < CHN; k++) {
            ulonglong2 xa = *reinterpret_cast<const ulonglong2*>(&xs[k * BS + p0]);
            ulonglong2 xb = *reinterpret_cast<const ulonglong2*>(&xs[k * BS + p0 + 4]);
            float4 wv = *reinterpret_cast<const float4*>(&M1s[k * MS + o0]);
            ull w0 = pack2(wv.x, wv.x), w1 = pack2(wv.y, wv.y);
            ull w2 = pack2(wv.z, wv.z), w3 = pack2(wv.w, wv.w);
            a1[0][0] = fma2(w0, xa.x, a1[0][0]); a1[0][1] = fma2(w0, xa.y, a1[0][1]);
            a1[0][2] = fma2(w0, xb.x, a1[0][2]); a1[0][3] = fma2(w0, xb.y, a1[0][3]);
            a1[1][0] = fma2(w1, xa.x, a1[1][0]); a1[1][1] = fma2(w1, xa.y, a1[1][1]);
            a1[1][2] = fma2(w1, xb.x, a1[1][2]); a1[1][3] = fma2(w1, xb.y, a1[1][3]);
            a1[2][0] = fma2(w2, xa.x, a1[2][0]); a1[2][1] = fma2(w2, xa.y, a1[2][1]);
            a1[2][2] = fma2(w2, xb.x, a1[2][2]); a1[2][3] = fma2(w2, xb.y, a1[2][3]);
            a1[3][0] = fma2(w3, xa.x, a1[3][0]); a1[3][1] = fma2(w3, xa.y, a1[3][1]);
            a1[3][2] = fma2(w3, xb.x, a1[3][2]); a1[3][3] = fma2(w3, xb.y, a1[3][3]);
        }

        // gelu -> u1
        #pragma unroll
        for (int i = 0; i < 4; i++) {
            #pragma unroll
            for (int j = 0; j < 4; j++) {
                float2 v = unpack2(a1[i][j]);
                v.x = gelu_exact(v.x);
                v.y = gelu_exact(v.y);
                *reinterpret_cast<float2*>(&u1[(o0 + i) * BS + p0 + 2 * j]) = v;
            }
        }
        __syncthreads();

        // GEMM2: o2 @ u1, then +x, gelu, store
        ull a2[4][4];
        #pragma unroll
        for (int i = 0; i < 4; i++)
            #pragma unroll
            for (int j = 0; j < 4; j++) a2[i][j] = 0ull;

        #pragma unroll 4
        for (int k = 0; k < CHN; k++) {
            ulonglong2 xa = *reinterpret_cast<const ulonglong2*>(&u1[k * BS + p0]);
            ulonglong2 xb = *reinterpret_cast<const ulonglong2*>(&u1[k * BS + p0 + 4]);
            float4 wv = *reinterpret_cast<const float4*>(&O2s[k * MS + o0]);
            ull w0 = pack2(wv.x, wv.x), w1 = pack2(wv.y, wv.y);
            ull w2 = pack2(wv.z, wv.z), w3 = pack2(wv.w, wv.w);
            a2[0][0] = fma2(w0, xa.x, a2[0][0]); a2[0][1] = fma2(w0, xa.y, a2[0][1]);
            a2[0][2] = fma2(w0, xb.x, a2[0][2]); a2[0][3] = fma2(w0, xb.y, a2[0][3]);
            a2[1][0] = fma2(w1, xa.x, a2[1][0]); a2[1][1] = fma2(w1, xa.y, a2[1][1]);
            a2[1][2] = fma2(w1, xb.x, a2[1][2]); a2[1][3] = fma2(w1, xb.y, a2[1][3]);
            a2[2][0] = fma2(w2, xa.x, a2[2][0]); a2[2][1] = fma2(w2, xa.y, a2[2][1]);
            a2[2][2] = fma2(w2, xb.x, a2[2][2]); a2[2][3] = fma2(w2, xb.y, a2[2][3]);
            a2[3][0] = fma2(w3, xa.x, a2[3][0]); a2[3][1] = fma2(w3, xa.y, a2[3][1]);
            a2[3][2] = fma2(w3, xb.x, a2[3][2]); a2[3][3] = fma2(w3, xb.y, a2[3][3]);
        }

        #pragma unroll
        for (int i = 0; i < 4; i++) {
            float* orow = out + ((size_t)b * CHN + o0 + i) * NPIX + nb;
            #pragma unroll
            for (int j = 0; j < 4; j++) {
                float2 v = unpack2(a2[i][j]);
                float2 xv = *reinterpret_cast<const float2*>(
                    &xs[(o0 + i) * BS + p0 + 2 * j]);
                float2 r;
                r.x = gelu_exact(v.x + xv.x);
                r.y = gelu_exact(v.y + xv.y);
                *reinterpret_cast<float2*>(&orow[p0 + 2 * j]) = r;
            }
        }
    }
}

// ============================================================================
extern "C" void kernel_launch(void* const* d_in, const int* in_sizes, int n_in,
                              void* d_out, int out_size) {
    const float* x     = (const float*)d_in[0];
    const float* qkv_w = (const float*)d_in[1];
    const float* o1_w  = (const float*)d_in[2];
    const float* o2_w  = (const float*)d_in[3];
    const float* klw   = (const float*)d_in[4];
    const float* klb   = (const float*)d_in[5];
    const float* vlw   = (const float*)d_in[6];
    const float* vlb   = (const float*)d_in[7];
    float* out = (float*)d_out;

    const int SMEM_A = (256 * WS + 256 * BS + 512) * (int)sizeof(float);   // ~203.8 KB
    const int SMEM_B = (2048 + 128 * 129) * (int)sizeof(float);            // ~74 KB
    const int SMEM_C = (2 * CHN * MS + 2 * CHN * BS) * (int)sizeof(float); // ~204.8 KB

    cudaFuncSetAttribute(kv_accum_kernel,  cudaFuncAttributeMaxDynamicSharedMemorySize, SMEM_A);
    cudaFuncSetAttribute(build_mats_kernel, cudaFuncAttributeMaxDynamicSharedMemorySize, SMEM_B);
    cudaFuncSetAttribute(mlp_kernel,       cudaFuncAttributeMaxDynamicSharedMemorySize, SMEM_C);

    zero_kv_kernel<<<16, 1024>>>();
    kv_accum_kernel<<<dim3(NPIX / (CHUNK * NCHUNK), BATCH), 256, SMEM_A>>>(
        x, qkv_w, klw, klb, vlw, vlb);
    build_mats_kernel<<<BATCH, 256, SMEM_B>>>(qkv_w, o1_w, o2_w);
    mlp_kernel<<<dim3(NPIX / (CHUNK * NCHUNK), BATCH), 256, SMEM_C>>>(x, out);
}

// round 2
// speedup vs baseline: 1.0963x; 1.0963x over previous
#include <cuda_runtime.h>
#include <math.h>

#define BATCH  8
#define CHN    128
#define HEADS  8
#define HC     16
#define NPIX   65536
#define EPS    1e-5f

#define BS     68     // kernel-A pixel-buffer row stride (floats)
#define WS     129    // kernel-A weight row stride (odd -> conflict-free scalar LDS)
#define BSM    64     // kernel-C pixel row stride (contiguous, conflict-free)
#define CHUNK  64     // pixels per smem chunk
#define NCHUNK 8      // chunks per block -> 512 pixels/block

typedef unsigned long long ull;

// -------- persistent device scratch --------
__device__ float g_kv[BATCH * HEADS * HC * HC];
__device__ float g_M1t[BATCH * CHN * CHN];   // fused matrix o1*(A+I), [k][o]
__device__ float g_o2t[CHN * CHN];           // o2_w transposed [k][o]

// -------- packed f32x2 helpers --------
static __device__ __forceinline__ ull fma2(ull a, ull b, ull c) {
    ull d;
    asm("fma.rn.f32x2 %0, %1, %2, %3;" : "=l"(d) : "l"(a), "l"(b), "l"(c));
    return d;
}
static __device__ __forceinline__ ull pack2(float lo, float hi) {
    ull d;
    asm("mov.b64 %0, {%1, %2};" : "=l"(d) : "f"(lo), "f"(hi));
    return d;
}
static __device__ __forceinline__ float2 unpack2(ull v) {
    float2 r;
    asm("mov.b64 {%0, %1}, %2;" : "=f"(r.x), "=f"(r.y) : "l"(v));
    return r;
}
static __device__ __forceinline__ float gelu_exact(float v) {
    return v * normcdff(v);
}

// ============================================================================
__global__ void zero_kv_kernel() {
    int i = blockIdx.x * blockDim.x + threadIdx.x;
    if (i < BATCH * HEADS * HC * HC) g_kv[i] = 0.f;
}

// ============================================================================
// Kernel A: k,v GEMM (256 out x 64 px x 128 K) + LN(16) + kv outer product.
// 512 threads: micro-tile 4 out x 8 px.
// ============================================================================
__global__ void __launch_bounds__(512, 1) kv_accum_kernel(
    const float* __restrict__ x, const float* __restrict__ qkv_w,
    const float* __restrict__ klw, const float* __restrict__ klb,
    const float* __restrict__ vlw, const float* __restrict__ vlb)
{
    extern __shared__ float sm[];
    float* Wsm = sm;                  // [256][WS]
    float* buf = sm + 256 * WS;       // [256][BS]  (rows 0..127 double as x tile)
    float* lw  = buf + 256 * BS;      // [256]
    float* lb  = lw + 256;            // [256]

    const int tid = threadIdx.x;
    const int b   = blockIdx.y;
    const int n0  = blockIdx.x * (CHUNK * NCHUNK);

    // k/v weights -> smem (coalesced reads, conflict-free scalar writes: WS odd)
    for (int idx = tid; idx < 256 * CHN; idx += 512) {
        int o = idx >> 7, c = idx & 127;
        int row = (o >> 5) * 48 + 16 + (o & 31);
        Wsm[o * WS + c] = qkv_w[row * CHN + c];
    }
    if (tid < 256) {
        int o = tid, h = o >> 5, d = o & 15;
        if (o & 16) { lw[o] = vlw[h * HC + d]; lb[o] = vlb[h * HC + d]; }
        else        { lw[o] = klw[h * HC + d]; lb[o] = klb[h * HC + d]; }
    }

    const int to = tid >> 3, tp = tid & 7;      // 64 out-groups x 8 px-groups
    const int p0 = tp * 8;
    const int warp = tid >> 5, lane = tid & 31;
    const int head = warp & 7, phalf = (warp >> 3) * 32;  // 16 warps: 8 heads x 2 px-halves
    const int dd = lane >> 1, e0 = (lane & 1) * 8;

    ull kvacc[8];
    #pragma unroll
    for (int t = 0; t < 8; t++) kvacc[t] = 0ull;

    for (int ch = 0; ch < NCHUNK; ch++) {
        const int nb = n0 + ch * CHUNK;
        __syncthreads();

        {   // x tile: 128 rows x 64 px, 512 threads x 4 float4
            int c = tid >> 2;
            int seg = (tid & 3) * 16;
            const float4* gx = reinterpret_cast<const float4*>(
                x + ((size_t)b * CHN + c) * NPIX + nb + seg);
            float4* dst = reinterpret_cast<float4*>(&buf[c * BS + seg]);
            dst[0] = gx[0]; dst[1] = gx[1]; dst[2] = gx[2]; dst[3] = gx[3];
        }
        __syncthreads();

        // GEMM: 4 out x 8 px per thread
        ull acc[4][4];
        #pragma unroll
        for (int i = 0; i < 4; i++)
            #pragma unroll
            for (int j = 0; j < 4; j++) acc[i][j] = 0ull;

        const float* Wr = &Wsm[(to * 4) * WS];
        #pragma unroll 8
        for (int k = 0; k < CHN; k++) {
            ulonglong2 xa = *reinterpret_cast<const ulonglong2*>(&buf[k * BS + p0]);
            ulonglong2 xb = *reinterpret_cast<const ulonglong2*>(&buf[k * BS + p0 + 4]);
            #pragma unroll
            for (int i = 0; i < 4; i++) {
                float w = Wr[i * WS + k];
                ull wp = pack2(w, w);
                acc[i][0] = fma2(wp, xa.x, acc[i][0]);
                acc[i][1] = fma2(wp, xa.y, acc[i][1]);
                acc[i][2] = fma2(wp, xb.x, acc[i][2]);
                acc[i][3] = fma2(wp, xb.y, acc[i][3]);
            }
        }
        __syncthreads();

        #pragma unroll
        for (int i = 0; i < 4; i++) {
            ull* dst = reinterpret_cast<ull*>(&buf[(to * 4 + i) * BS + p0]);
            dst[0] = acc[i][0]; dst[1] = acc[i][1];
            dst[2] = acc[i][2]; dst[3] = acc[i][3];
        }
        __syncthreads();

        // LayerNorm: 512 tasks (pixel p, head hh), each normalizes k then v.
        {
            int p  = tid & 63;
            int hh = tid >> 6;
            #pragma unroll
            for (int part = 0; part < 2; part++) {
                int rbase = hh * 32 + part * 16;
                float t[16]; float s = 0.f;
                #pragma unroll
                for (int d = 0; d < 16; d++) { t[d] = buf[(rbase + d) * BS + p]; s += t[d]; }
                float m = s * (1.f / 16.f);
                float var = 0.f;
                #pragma unroll
                for (int d = 0; d < 16; d++) { float dv = t[d] - m; var += dv * dv; }
                float inv = 1.f / (sqrtf(var * (1.f / 15.f)) + EPS);
                #pragma unroll
                for (int d = 0; d < 16; d++)
                    buf[(rbase + d) * BS + p] =
                        lw[rbase + d] * ((t[d] - m) * inv) + lb[rbase + d];
            }
        }
        __syncthreads();

        // kv outer product: warp -> (head, pixel half), lane -> (d, e0..e0+7)
        const float* kr = &buf[(head * 32 + dd) * BS + phalf];
        #pragma unroll 4
        for (int p = 0; p < 32; p += 2) {
            ull k2 = *reinterpret_cast<const ull*>(&kr[p]);
            #pragma unroll
            for (int t = 0; t < 8; t++) {
                ull v2 = *reinterpret_cast<const ull*>(
                    &buf[(head * 32 + 16 + e0 + t) * BS + phalf + p]);
                kvacc[t] = fma2(k2, v2, kvacc[t]);
            }
        }
    }

    #pragma unroll
    for (int t = 0; t < 8; t++) {
        float2 v = unpack2(kvacc[t]);
        atomicAdd(&g_kv[((b * HEADS + head) * HC + dd) * HC + e0 + t], v.x + v.y);
    }
}

// ============================================================================
// Kernel B: fold attention into per-batch 128x128 matrix (tiny).
// ============================================================================
__global__ void build_mats_kernel(const float* __restrict__ qkv_w,
                                  const float* __restrict__ o1_w,
                                  const float* __restrict__ o2_w)
{
    extern __shared__ float sm[];
    float* kvs = sm;            // 2048
    float* As  = sm + 2048;     // [128][129]
    const int tid = threadIdx.x;
    const int b   = blockIdx.x;

    for (int i = tid; i < HEADS * HC * HC; i += 256)
        kvs[i] = g_kv[b * HEADS * HC * HC + i] * (1.f / NPIX);
    __syncthreads();

    for (int idx = tid; idx < CHN * CHN; idx += 256) {
        int j = idx >> 7, c = idx & 127;
        int h = j >> 4,  e = j & 15;
        float s = 0.f;
        #pragma unroll
        for (int d = 0; d < HC; d++)
            s += qkv_w[(h * 48 + d) * CHN + c] * kvs[(h * HC + d) * HC + e];
        As[j * 129 + c] = s;
    }
    __syncthreads();

    for (int idx = tid; idx < CHN * CHN; idx += 256) {
        int c = idx >> 7, o = idx & 127;
        float s = o1_w[o * CHN + c];            // identity term
        for (int j = 0; j < CHN; j++)
            s += o1_w[o * CHN + j] * As[j * 129 + c];
        g_M1t[((size_t)b * CHN + c) * CHN + o] = s;
    }
    if (b == 0) {
        for (int idx = tid; idx < CHN * CHN; idx += 256) {
            int c = idx >> 7, o = idx & 127;
            g_o2t[c * CHN + o] = o2_w[o * CHN + c];
        }
    }
}

// ============================================================================
// Kernel C: out = gelu( o2 @ gelu( M1[b] @ x ) + x )
// 512 threads: micro-tile 4 out x 4 px; weights [k][o] stride 128 (float4
// broadcast loads), pixel rows contiguous 64 floats (conflict-free).
// ============================================================================
__global__ void __launch_bounds__(512, 1) mlp_kernel(
    const float* __restrict__ x, float* __restrict__ out)
{
    extern __shared__ float sm[];
    float* M1s = sm;                   // [128][128]
    float* O2s = M1s + CHN * CHN;      // [128][128]
    float* xs  = O2s + CHN * CHN;      // [128][BSM]
    float* u1  = xs  + CHN * BSM;      // [128][BSM]

    const int tid = threadIdx.x;
    const int b   = blockIdx.y;
    const int n0  = blockIdx.x * (CHUNK * NCHUNK);

    {   // weight tiles: straight float4 copies (layout already [k][o])
        const float4* src1 = reinterpret_cast<const float4*>(g_M1t + (size_t)b * CHN * CHN);
        const float4* src2 = reinterpret_cast<const float4*>(g_o2t);
        float4* d1 = reinterpret_cast<float4*>(M1s);
        float4* d2 = reinterpret_cast<float4*>(O2s);
        #pragma unroll
        for (int q = 0; q < 8; q++) {
            d1[tid + q * 512] = src1[tid + q * 512];
            d2[tid + q * 512] = src2[tid + q * 512];
        }
    }

    const int to = tid >> 4, tp = tid & 15;   // 32 out-groups x 16 px-groups
    const int o0 = to * 4, p0 = tp * 4;

    for (int ch = 0; ch < NCHUNK; ch++) {
        const int nb = n0 + ch * CHUNK;
        __syncthreads();

        {   // x tile
            int c = tid >> 2;
            int seg = (tid & 3) * 16;
            const float4* gx = reinterpret_cast<const float4*>(
                x + ((size_t)b * CHN + c) * NPIX + nb + seg);
            float4* dst = reinterpret_cast<float4*>(&xs[c * BSM + seg]);
            dst[0] = gx[0]; dst[1] = gx[1]; dst[2] = gx[2]; dst[3] = gx[3];
        }
        __syncthreads();

        // GEMM1: u1 = gelu(M1 @ x)
        ull a1[4][2];
        #pragma unroll
        for (int i = 0; i < 4; i++) { a1[i][0] = 0ull; a1[i][1] = 0ull; }

        #pragma unroll 8
        for (int k = 0; k < CHN; k++) {
            ulonglong2 xv = *reinterpret_cast<const ulonglong2*>(&xs[k * BSM + p0]);
            float4 wv = *reinterpret_cast<const float4*>(&M1s[k * CHN + o0]);
            ull w0 = pack2(wv.x, wv.x), w1 = pack2(wv.y, wv.y);
            ull w2 = pack2(wv.z, wv.z), w3 = pack2(wv.w, wv.w);
            a1[0][0] = fma2(w0, xv.x, a1[0][0]); a1[0][1] = fma2(w0, xv.y, a1[0][1]);
            a1[1][0] = fma2(w1, xv.x, a1[1][0]); a1[1][1] = fma2(w1, xv.y, a1[1][1]);
            a1[2][0] = fma2(w2, xv.x, a1[2][0]); a1[2][1] = fma2(w2, xv.y, a1[2][1]);
            a1[3][0] = fma2(w3, xv.x, a1[3][0]); a1[3][1] = fma2(w3, xv.y, a1[3][1]);
        }

        #pragma unroll
        for (int i = 0; i < 4; i++) {
            float2 v0 = unpack2(a1[i][0]);
            float2 v1 = unpack2(a1[i][1]);
            float4 r;
            r.x = gelu_exact(v0.x); r.y = gelu_exact(v0.y);
            r.z = gelu_exact(v1.x); r.w = gelu_exact(v1.y);
            *reinterpret_cast<float4*>(&u1[(o0 + i) * BSM + p0]) = r;
        }
        __syncthreads();

        // GEMM2: o2 @ u1, +x, gelu, store
        ull a2[4][2];
        #pragma unroll
        for (int i = 0; i < 4; i++) { a2[i][0] = 0ull; a2[i][1] = 0ull; }

        #pragma unroll 8
        for (int k = 0; k < CHN; k++) {
            ulonglong2 xv = *reinterpret_cast<const ulonglong2*>(&u1[k * BSM + p0]);
            float4 wv = *reinterpret_cast<const float4*>(&O2s[k * CHN + o0]);
            ull w0 = pack2(wv.x, wv.x), w1 = pack2(wv.y, wv.y);
            ull w2 = pack2(wv.z, wv.z), w3 = pack2(wv.w, wv.w);
            a2[0][0] = fma2(w0, xv.x, a2[0][0]); a2[0][1] = fma2(w0, xv.y, a2[0][1]);
            a2[1][0] = fma2(w1, xv.x, a2[1][0]); a2[1][1] = fma2(w1, xv.y, a2[1][1]);
            a2[2][0] = fma2(w2, xv.x, a2[2][0]); a2[2][1] = fma2(w2, xv.y, a2[2][1]);
            a2[3][0] = fma2(w3, xv.x, a2[3][0]); a2[3][1] = fma2(w3, xv.y, a2[3][1]);
        }

        #pragma unroll
        for (int i = 0; i < 4; i++) {
            float4 xv = *reinterpret_cast<const float4*>(&xs[(o0 + i) * BSM + p0]);
            float2 v0 = unpack2(a2[i][0]);
            float2 v1 = unpack2(a2[i][1]);
            float4 r;
            r.x = gelu_exact(v0.x + xv.x);
            r.y = gelu_exact(v0.y + xv.y);
            r.z = gelu_exact(v1.x + xv.z);
            r.w = gelu_exact(v1.y + xv.w);
            *reinterpret_cast<float4*>(
                out + ((size_t)b * CHN + o0 + i) * NPIX + nb + p0) = r;
        }
    }
}

// ============================================================================
extern "C" void kernel_launch(void* const* d_in, const int* in_sizes, int n_in,
                              void* d_out, int out_size) {
    const float* x     = (const float*)d_in[0];
    const float* qkv_w = (const float*)d_in[1];
    const float* o1_w  = (const float*)d_in[2];
    const float* o2_w  = (const float*)d_in[3];
    const float* klw   = (const float*)d_in[4];
    const float* klb   = (const float*)d_in[5];
    const float* vlw   = (const float*)d_in[6];
    const float* vlb   = (const float*)d_in[7];
    float* out = (float*)d_out;

    const int SMEM_A = (256 * WS + 256 * BS + 512) * (int)sizeof(float);     // ~199 KB
    const int SMEM_B = (2048 + 128 * 129) * (int)sizeof(float);              // ~74 KB
    const int SMEM_C = (2 * CHN * CHN + 2 * CHN * BSM) * (int)sizeof(float); // 192 KB

    cudaFuncSetAttribute(kv_accum_kernel,   cudaFuncAttributeMaxDynamicSharedMemorySize, SMEM_A);
    cudaFuncSetAttribute(build_mats_kernel, cudaFuncAttributeMaxDynamicSharedMemorySize, SMEM_B);
    cudaFuncSetAttribute(mlp_kernel,        cudaFuncAttributeMaxDynamicSharedMemorySize, SMEM_C);

    const int blocks_x = NPIX / (CHUNK * NCHUNK);   // 128
    zero_kv_kernel<<<16, 1024>>>();
    kv_accum_kernel<<<dim3(blocks_x, BATCH), 512, SMEM_A>>>(
        x, qkv_w, klw, klb, vlw, vlb);
    build_mats_kernel<<<BATCH, 256, SMEM_B>>>(qkv_w, o1_w, o2_w);
    mlp_kernel<<<dim3(blocks_x, BATCH), 512, SMEM_C>>>(x, out);
}

// round 6
// speedup vs baseline: 2.9135x; 2.6577x over previous
#include <cuda_runtime.h>
#include <cuda_bf16.h>
#include <math.h>
#include <stdint.h>

#define BATCH  8
#define CHN    128
#define HEADS  8
#define HC     16
#define NPIX   65536
#define EPS    1e-5f

#define PXA    32      // kernel A pixels per chunk
#define NCHA   16      // chunks per CTA (A)  -> 512 px/CTA
#define PXC    64      // kernel C pixels per chunk
#define NCHC   8       // chunks per CTA (C)  -> 512 px/CTA
#define WSTR   136     // bf16 row stride (272B): conflict-free ldmatrix

typedef unsigned long long ull;
typedef unsigned int u32;

// ---------------- persistent device scratch ----------------
__device__ float g_kv[BATCH * HEADS * HC * HC];                      // 16384 elems
__device__ __align__(16) __nv_bfloat16 g_wkv[2][256][WSTR];          // kv weights hi/lo
__device__ __align__(16) __nv_bfloat16 g_m1[BATCH][2][CHN][WSTR];    // fused M1 hi/lo
__device__ __align__(16) __nv_bfloat16 g_o2[2][CHN][WSTR];           // o2 hi/lo

// ---------------- helpers ----------------
static __device__ __forceinline__ ull fma2(ull a, ull b, ull c) {
    ull d;
    asm("fma.rn.f32x2 %0, %1, %2, %3;" : "=l"(d) : "l"(a), "l"(b), "l"(c));
    return d;
}
static __device__ __forceinline__ float2 unpack2(ull v) {
    float2 r;
    asm("mov.b64 {%0, %1}, %2;" : "=f"(r.x), "=f"(r.y) : "l"(v));
    return r;
}
static __device__ __forceinline__ float gelu_exact(float v) { return v * normcdff(v); }

static __device__ __forceinline__ u32 smem_u32(const void* p) {
    u32 a;
    asm("{ .reg .u64 t; cvta.to.shared.u64 t, %1; cvt.u32.u64 %0, t; }" : "=r"(a) : "l"(p));
    return a;
}

#define LDSM4(r0, r1, r2, r3, a)                                           \
    asm volatile("ldmatrix.sync.aligned.m8n8.x4.shared.b16 {%0,%1,%2,%3}, [%4];" \
        : "=r"(r0), "=r"(r1), "=r"(r2), "=r"(r3) : "r"(a))

static __device__ __forceinline__ void mma16816(float* d, const u32* a, const u32* b) {
    asm volatile(
        "mma.sync.aligned.m16n8k16.row.col.f32.bf16.bf16.f32 "
        "{%0,%1,%2,%3}, {%4,%5,%6,%7}, {%8,%9}, {%0,%1,%2,%3};"
        : "+f"(d[0]), "+f"(d[1]), "+f"(d[2]), "+f"(d[3])
        : "r"(a[0]), "r"(a[1]), "r"(a[2]), "r"(a[3]), "r"(b[0]), "r"(b[1]));
}

static __device__ __forceinline__ void split_bf16(float w, __nv_bfloat16& hi, __nv_bfloat16& lo) {
    hi = __float2bfloat16(w);
    lo = __float2bfloat16(w - __bfloat162float(hi));
}

// ============================================================================
__global__ void zero_kv_kernel() {
    int i = blockIdx.x * blockDim.x + threadIdx.x;
    if (i < BATCH * HEADS * HC * HC) g_kv[i] = 0.f;
}

// Split k/v weight rows to bf16 hi/lo, padded [o][WSTR].
// local row o: head=o>>5, (o&31)<16 -> k rows, else v; qkv row=(o>>5)*48+16+(o&31)
__global__ void prep_wkv_kernel(const float* __restrict__ qkv_w) {
    int idx = blockIdx.x * blockDim.x + threadIdx.x;   // 32768
    int o = idx >> 7, c = idx & 127;
    int row = (o >> 5) * 48 + 16 + (o & 31);
    __nv_bfloat16 hi, lo;
    split_bf16(qkv_w[row * CHN + c], hi, lo);
    g_wkv[0][o][c] = hi;
    g_wkv[1][o][c] = lo;
}

// ============================================================================
// Kernel A: k,v = W_kv @ x  (mma.sync bf16, 3-term split), LN(16), kv outer.
// 512 threads = 16 warps: 8(M) x 2(N); warp tile 32 out x 16 px.
// ============================================================================
__global__ void __launch_bounds__(512, 1) kv_accum_kernel(
    const float* __restrict__ x,
    const float* __restrict__ klw, const float* __restrict__ klb,
    const float* __restrict__ vlw, const float* __restrict__ vlb)
{
    extern __shared__ __align__(16) unsigned char sm[];
    const int OFF_WH = 0;          // 256*WSTR*2 = 69632
    const int OFF_WL = 69632;
    const int OFF_XH = 139264;     // 32*WSTR*2 = 8704
    const int OFF_XL = 147968;
    const int OFF_LN = 156672;     // 256*34*4 = 34816
    const int OFF_LW = 191488;
    const int OFF_LB = 192512;     // total 193536

    const u32 sbase = smem_u32(sm);
    float* lnbuf = (float*)(sm + OFF_LN);
    float* lw = (float*)(sm + OFF_LW);
    float* lb = (float*)(sm + OFF_LB);

    const int tid = threadIdx.x;
    const int wid = tid >> 5, lane = tid & 31;
    const int b = blockIdx.y;
    const int n0 = blockIdx.x * (PXA * NCHA);

    {   // weight images -> smem (139264 B = 8704 float4 = 17*512)
        const float4* src = (const float4*)&g_wkv[0][0][0];
        float4* dst = (float4*)(sm + OFF_WH);
        #pragma unroll
        for (int i = 0; i < 17; i++) dst[tid + i * 512] = src[tid + i * 512];
    }
    if (tid < 256) {
        int o = tid, h = o >> 5, d = o & 15;
        if (o & 16) { lw[o] = vlw[h * HC + d]; lb[o] = vlb[h * HC + d]; }
        else        { lw[o] = klw[h * HC + d]; lb[o] = klb[h * HC + d]; }
    }

    // warp GEMM mapping
    const int wm = wid & 7, wn = wid >> 3;
    const int m_base = wm * 32, n_base = wn * 16;
    const int a_row = m_base + (lane & 15), a_col8 = (lane >> 4) * 8;
    const u32 aoff = (u32)(a_row * WSTR + a_col8) * 2;
    const int b_row = n_base + (lane & 7) + (lane >> 4) * 8;
    const int b_col8 = ((lane >> 3) & 1) * 8;
    const u32 boff = (u32)(b_row * WSTR + b_col8) * 2;

    // loader mapping: channel, 8-px segment
    const int lc = tid >> 2, lseg = (tid & 3) * 8;
    // outer-product mapping
    const int ohead = wid & 7, ophalf = (wid >> 3) * 16;
    const int odd = lane >> 1, oe0 = (lane & 1) * 8;

    ull kvacc[8];
    #pragma unroll
    for (int t = 0; t < 8; t++) kvacc[t] = 0ull;

    for (int ch = 0; ch < NCHA; ch++) {
        const int nb = n0 + ch * PXA;
        __syncthreads();   // prev-chunk consumers done / weight copy visible

        {   // x tile -> [px][c] bf16 hi/lo
            const float* gx = x + ((size_t)b * CHN + lc) * NPIX + nb + lseg;
            float4 v0 = *(const float4*)gx;
            float4 v1 = *(const float4*)(gx + 4);
            float vv[8] = {v0.x, v0.y, v0.z, v0.w, v1.x, v1.y, v1.z, v1.w};
            __nv_bfloat16* xh = (__nv_bfloat16*)(sm + OFF_XH);
            __nv_bfloat16* xl = (__nv_bfloat16*)(sm + OFF_XL);
            #pragma unroll
            for (int j = 0; j < 8; j++) {
                __nv_bfloat16 hi, lo;
                split_bf16(vv[j], hi, lo);
                xh[(lseg + j) * WSTR + lc] = hi;
                xl[(lseg + j) * WSTR + lc] = lo;
            }
        }
        __syncthreads();

        // GEMM: 2 m16-tiles x 2 n8-tiles, K=128 in 8 steps, 3-term split
        float acc[2][2][4];
        #pragma unroll
        for (int i = 0; i < 2; i++)
            #pragma unroll
            for (int j = 0; j < 2; j++)
                #pragma unroll
                for (int q = 0; q < 4; q++) acc[i][j][q] = 0.f;

        #pragma unroll
        for (int ks = 0; ks < 8; ks++) {
            const u32 kk = ks * 32;   // 16 bf16 = 32 bytes
            u32 Ah[2][4], Al[2][4], Bh[4], Bl[4];
            LDSM4(Ah[0][0], Ah[0][1], Ah[0][2], Ah[0][3], sbase + OFF_WH + aoff + kk);
            LDSM4(Ah[1][0], Ah[1][1], Ah[1][2], Ah[1][3], sbase + OFF_WH + aoff + kk + 16 * WSTR * 2);
            LDSM4(Al[0][0], Al[0][1], Al[0][2], Al[0][3], sbase + OFF_WL + aoff + kk);
            LDSM4(Al[1][0], Al[1][1], Al[1][2], Al[1][3], sbase + OFF_WL + aoff + kk + 16 * WSTR * 2);
            LDSM4(Bh[0], Bh[1], Bh[2], Bh[3], sbase + OFF_XH + boff + kk);
            LDSM4(Bl[0], Bl[1], Bl[2], Bl[3], sbase + OFF_XL + boff + kk);
            #pragma unroll
            for (int i = 0; i < 2; i++) {
                #pragma unroll
                for (int j = 0; j < 2; j++) {
                    mma16816(acc[i][j], Ah[i], Bh + j * 2);
                    mma16816(acc[i][j], Al[i], Bh + j * 2);
                    mma16816(acc[i][j], Ah[i], Bl + j * 2);
                }
            }
        }

        // D -> lnbuf[out][px] (stride 34)
        #pragma unroll
        for (int i = 0; i < 2; i++) {
            #pragma unroll
            for (int j = 0; j < 2; j++) {
                int px = n_base + j * 8 + (lane & 3) * 2;
                int o0 = m_base + i * 16 + (lane >> 2);
                *(float2*)&lnbuf[o0 * 34 + px]       = make_float2(acc[i][j][0], acc[i][j][1]);
                *(float2*)&lnbuf[(o0 + 8) * 34 + px] = make_float2(acc[i][j][2], acc[i][j][3]);
            }
        }
        __syncthreads();

        {   // LayerNorm: 512 tasks = 32 px x 8 heads x {k,v}
            int p = tid & 31, hh = (tid >> 5) & 7, part = tid >> 8;
            int rbase = hh * 32 + part * 16;
            float t[16]; float s = 0.f;
            #pragma unroll
            for (int d = 0; d < 16; d++) { t[d] = lnbuf[(rbase + d) * 34 + p]; s += t[d]; }
            float m = s * (1.f / 16.f);
            float var = 0.f;
            #pragma unroll
            for (int d = 0; d < 16; d++) { float dv = t[d] - m; var += dv * dv; }
            float inv = 1.f / (sqrtf(var * (1.f / 15.f)) + EPS);
            #pragma unroll
            for (int d = 0; d < 16; d++)
                lnbuf[(rbase + d) * 34 + p] =
                    lw[rbase + d] * ((t[d] - m) * inv) + lb[rbase + d];
        }
        __syncthreads();

        {   // kv outer product (f32x2), 16 px per warp
            const float* kr = &lnbuf[(ohead * 32 + odd) * 34 + ophalf];
            #pragma unroll
            for (int p = 0; p < 16; p += 2) {
                ull k2 = *(const ull*)&kr[p];
                #pragma unroll
                for (int t = 0; t < 8; t++) {
                    ull v2 = *(const ull*)&lnbuf[(ohead * 32 + 16 + oe0 + t) * 34 + ophalf + p];
                    kvacc[t] = fma2(k2, v2, kvacc[t]);
                }
            }
        }
    }

    #pragma unroll
    for (int t = 0; t < 8; t++) {
        float2 v = unpack2(kvacc[t]);
        atomicAdd(&g_kv[((b * HEADS + ohead) * HC + odd) * HC + oe0 + t], v.x + v.y);
    }
}

// ============================================================================
// Kernel B: fold attention -> M1[b] = o1_w @ (A + I); emit bf16 hi/lo images.
// ============================================================================
__global__ void build_mats_kernel(const float* __restrict__ qkv_w,
                                  const float* __restrict__ o1_w,
                                  const float* __restrict__ o2_w)
{
    extern __shared__ float smf[];
    float* kvs = smf;           // 2048
    float* As  = smf + 2048;    // [128][129]
    const int tid = threadIdx.x;
    const int b   = blockIdx.x;

    for (int i = tid; i < HEADS * HC * HC; i += 256)
        kvs[i] = g_kv[b * HEADS * HC * HC + i] * (1.f / NPIX);
    __syncthreads();

    for (int idx = tid; idx < CHN * CHN; idx += 256) {
        int j = idx >> 7, c = idx & 127;
        int h = j >> 4, e = j & 15;
        float s = 0.f;
        #pragma unroll
        for (int d = 0; d < HC; d++)
            s += qkv_w[(h * 48 + d) * CHN + c] * kvs[(h * HC + d) * HC + e];
        As[j * 129 + c] = s;
    }
    __syncthreads();

    for (int idx = tid; idx < CHN * CHN; idx += 256) {
        int o = idx >> 7, c = idx & 127;
        float s = o1_w[o * CHN + c];   // identity term
        for (int j = 0; j < CHN; j++)
            s += o1_w[o * CHN + j] * As[j * 129 + c];
        __nv_bfloat16 hi, lo;
        split_bf16(s, hi, lo);
        g_m1[b][0][o][c] = hi;
        g_m1[b][1][o][c] = lo;
    }
    if (b == 0) {
        for (int idx = tid; idx < CHN * CHN; idx += 256) {
            int o = idx >> 7, c = idx & 127;
            __nv_bfloat16 hi, lo;
            split_bf16(o2_w[o * CHN + c], hi, lo);
            g_o2[0][o][c] = hi;
            g_o2[1][o][c] = lo;
        }
    }
}

// ============================================================================
// Kernel C: out = gelu( o2 @ gelu( M1[b] @ x ) + x ), both GEMMs mma.sync.
// 512 threads = 16 warps: 4(M) x 4(N); warp tile 32 out x 16 px; chunk 64 px.
// ============================================================================
__global__ void __launch_bounds__(512, 1) mlp_kernel(
    const float* __restrict__ x, float* __restrict__ out)
{
    extern __shared__ __align__(16) unsigned char sm[];
    const int OFF_M1H = 0;          // 128*WSTR*2 = 34816
    const int OFF_M1L = 34816;
    const int OFF_O2H = 69632;
    const int OFF_O2L = 104448;
    const int OFF_XH  = 139264;     // 64*WSTR*2 = 17408
    const int OFF_XL  = 156672;
    const int OFF_UH  = 174080;
    const int OFF_UL  = 191488;     // total 208896

    const u32 sbase = smem_u32(sm);
    const int tid = threadIdx.x;
    const int wid = tid >> 5, lane = tid & 31;
    const int b = blockIdx.y;
    const int n0 = blockIdx.x * (PXC * NCHC);

    {   // weight images -> smem: 69632 B each pair = 4352 float4 = 8*512 + 256
        const float4* s1 = (const float4*)&g_m1[b][0][0][0];
        const float4* s2 = (const float4*)&g_o2[0][0][0];
        float4* d1 = (float4*)(sm + OFF_M1H);
        float4* d2 = (float4*)(sm + OFF_O2H);
        #pragma unroll
        for (int i = 0; i < 8; i++) {
            d1[tid + i * 512] = s1[tid + i * 512];
            d2[tid + i * 512] = s2[tid + i * 512];
        }
        if (tid < 256) {
            d1[tid + 4096] = s1[tid + 4096];
            d2[tid + 4096] = s2[tid + 4096];
        }
    }

    const int wm = wid & 3, wn = wid >> 2;
    const int m_base = wm * 32, n_base = wn * 16;
    const u32 aoff = (u32)((m_base + (lane & 15)) * WSTR + (lane >> 4) * 8) * 2;
    const u32 boff = (u32)((n_base + (lane & 7) + (lane >> 4) * 8) * WSTR
                           + ((lane >> 3) & 1) * 8) * 2;

    const int lc = tid >> 2, lseg = (tid & 3) * 16;   // loader: channel, 16-px seg

    for (int ch = 0; ch < NCHC; ch++) {
        const int nb = n0 + ch * PXC;
        {   // x tile -> [px][c] bf16 hi/lo
            const float* gx = x + ((size_t)b * CHN + lc) * NPIX + nb + lseg;
            __nv_bfloat16* xh = (__nv_bfloat16*)(sm + OFF_XH);
            __nv_bfloat16* xl = (__nv_bfloat16*)(sm + OFF_XL);
            #pragma unroll
            for (int q = 0; q < 4; q++) {
                float4 v = *(const float4*)(gx + q * 4);
                float vv[4] = {v.x, v.y, v.z, v.w};
                #pragma unroll
                for (int j = 0; j < 4; j++) {
                    __nv_bfloat16 hi, lo;
                    split_bf16(vv[j], hi, lo);
                    xh[(lseg + q * 4 + j) * WSTR + lc] = hi;
                    xl[(lseg + q * 4 + j) * WSTR + lc] = lo;
                }
            }
        }
        __syncthreads();

        // ---- GEMM1: D1 = M1 @ x ----
        float a1[2][2][4];
        #pragma unroll
        for (int i = 0; i < 2; i++)
            #pragma unroll
            for (int j = 0; j < 2; j++)
                #pragma unroll
                for (int q = 0; q < 4; q++) a1[i][j][q] = 0.f;

        #pragma unroll
        for (int ks = 0; ks < 8; ks++) {
            const u32 kk = ks * 32;
            u32 Ah[2][4], Al[2][4], Bh[4], Bl[4];
            LDSM4(Ah[0][0], Ah[0][1], Ah[0][2], Ah[0][3], sbase + OFF_M1H + aoff + kk);
            LDSM4(Ah[1][0], Ah[1][1], Ah[1][2], Ah[1][3], sbase + OFF_M1H + aoff + kk + 16 * WSTR * 2);
            LDSM4(Al[0][0], Al[0][1], Al[0][2], Al[0][3], sbase + OFF_M1L + aoff + kk);
            LDSM4(Al[1][0], Al[1][1], Al[1][2], Al[1][3], sbase + OFF_M1L + aoff + kk + 16 * WSTR * 2);
            LDSM4(Bh[0], Bh[1], Bh[2], Bh[3], sbase + OFF_XH + boff + kk);
            LDSM4(Bl[0], Bl[1], Bl[2], Bl[3], sbase + OFF_XL + boff + kk);
            #pragma unroll
            for (int i = 0; i < 2; i++)
                #pragma unroll
                for (int j = 0; j < 2; j++) {
                    mma16816(a1[i][j], Ah[i], Bh + j * 2);
                    mma16816(a1[i][j], Al[i], Bh + j * 2);
                    mma16816(a1[i][j], Ah[i], Bl + j * 2);
                }
        }

        {   // epilogue1: u = gelu(D1), split, store transposed [px][chan]
            __nv_bfloat16* uh = (__nv_bfloat16*)(sm + OFF_UH);
            __nv_bfloat16* ul = (__nv_bfloat16*)(sm + OFF_UL);
            #pragma unroll
            for (int i = 0; i < 2; i++)
                #pragma unroll
                for (int j = 0; j < 2; j++) {
                    int px = n_base + j * 8 + (lane & 3) * 2;
                    int o0 = m_base + i * 16 + (lane >> 2);
                    #pragma unroll
                    for (int q = 0; q < 4; q++) {
                        int pp = px + (q & 1);
                        int oo = o0 + (q >> 1) * 8;
                        float u = gelu_exact(a1[i][j][q]);
                        __nv_bfloat16 hi, lo;
                        split_bf16(u, hi, lo);
                        uh[pp * WSTR + oo] = hi;
                        ul[pp * WSTR + oo] = lo;
                    }
                }
        }
        __syncthreads();

        // ---- GEMM2: D2 = o2 @ u ----
        float a2[2][2][4];
        #pragma unroll
        for (int i = 0; i < 2; i++)
            #pragma unroll
            for (int j = 0; j < 2; j++)
                #pragma unroll
                for (int q = 0; q < 4; q++) a2[i][j][q] = 0.f;

        #pragma unroll
        for (int ks = 0; ks < 8; ks++) {
            const u32 kk = ks * 32;
            u32 Ah[2][4], Al[2][4], Bh[4], Bl[4];
            LDSM4(Ah[0][0], Ah[0][1], Ah[0][2], Ah[0][3], sbase + OFF_O2H + aoff + kk);
            LDSM4(Ah[1][0], Ah[1][1], Ah[1][2], Ah[1][3], sbase + OFF_O2H + aoff + kk + 16 * WSTR * 2);
            LDSM4(Al[0][0], Al[0][1], Al[0][2], Al[0][3], sbase + OFF_O2L + aoff + kk);
            LDSM4(Al[1][0], Al[1][1], Al[1][2], Al[1][3], sbase + OFF_O2L + aoff + kk + 16 * WSTR * 2);
            LDSM4(Bh[0], Bh[1], Bh[2], Bh[3], sbase + OFF_UH + boff + kk);
            LDSM4(Bl[0], Bl[1], Bl[2], Bl[3], sbase + OFF_UL + boff + kk);
            #pragma unroll
            for (int i = 0; i < 2; i++)
                #pragma unroll
                for (int j = 0; j < 2; j++) {
                    mma16816(a2[i][j], Ah[i], Bh + j * 2);
                    mma16816(a2[i][j], Al[i], Bh + j * 2);
                    mma16816(a2[i][j], Ah[i], Bl + j * 2);
                }
        }

        {   // epilogue2: out = gelu(D2 + x), direct LDG/STG (float2)
            #pragma unroll
            for (int i = 0; i < 2; i++)
                #pragma unroll
                for (int j = 0; j < 2; j++) {
                    int px = nb + n_base + j * 8 + (lane & 3) * 2;
                    int o0 = m_base + i * 16 + (lane >> 2);
                    #pragma unroll
                    for (int half = 0; half < 2; half++) {
                        int oo = o0 + half * 8;
                        const float* xr = x + ((size_t)b * CHN + oo) * NPIX + px;
                        float* orow = out + ((size_t)b * CHN + oo) * NPIX + px;
                        float2 xv = *(const float2*)xr;
                        float2 r;
                        r.x = gelu_exact(a2[i][j][half * 2 + 0] + xv.x);
                        r.y = gelu_exact(a2[i][j][half * 2 + 1] + xv.y);
                        *(float2*)orow = r;
                    }
                }
        }
        __syncthreads();   // U/X consumers done before next chunk overwrites
    }
}

// ============================================================================
extern "C" void kernel_launch(void* const* d_in, const int* in_sizes, int n_in,
                              void* d_out, int out_size) {
    const float* x     = (const float*)d_in[0];
    const float* qkv_w = (const float*)d_in[1];
    const float* o1_w  = (const float*)d_in[2];
    const float* o2_w  = (const float*)d_in[3];
    const float* klw   = (const float*)d_in[4];
    const float* klb   = (const float*)d_in[5];
    const float* vlw   = (const float*)d_in[6];
    const float* vlb   = (const float*)d_in[7];
    float* out = (float*)d_out;

    const int SMEM_A = 193536;
    const int SMEM_B = (2048 + 128 * 129) * (int)sizeof(float);
    const int SMEM_C = 208896;

    cudaFuncSetAttribute(kv_accum_kernel,   cudaFuncAttributeMaxDynamicSharedMemorySize, SMEM_A);
    cudaFuncSetAttribute(build_mats_kernel, cudaFuncAttributeMaxDynamicSharedMemorySize, SMEM_B);
    cudaFuncSetAttribute(mlp_kernel,        cudaFuncAttributeMaxDynamicSharedMemorySize, SMEM_C);

    // FIX: 16384 g_kv elements need 16384 threads (was 8*512=4096 -> stale
    // accumulators on replays -> post-timing divergence).
    zero_kv_kernel<<<32, 512>>>();
    prep_wkv_kernel<<<64, 512>>>(qkv_w);
    kv_accum_kernel<<<dim3(NPIX / (PXA * NCHA), BATCH), 512, SMEM_A>>>(
        x, klw, klb, vlw, vlb);
    build_mats_kernel<<<BATCH, 256, SMEM_B>>>(qkv_w, o1_w, o2_w);
    mlp_kernel<<<dim3(NPIX / (PXC * NCHC), BATCH), 512, SMEM_C>>>(x, out);
}

// round 7
// speedup vs baseline: 3.3195x; 1.1394x over previous
#include <cuda_runtime.h>
#include <cuda_bf16.h>
#include <math.h>
#include <stdint.h>

#define BATCH  8
#define CHN    128
#define HEADS  8
#define HC     16
#define NPIX   65536
#define EPS    1e-5f

#define PXA    32      // kernel A pixels per chunk
#define NCHA   16      // chunks per CTA (A)  -> 512 px/CTA
#define PXC    64      // kernel C pixels per chunk
#define NCHC   8       // chunks per CTA (C)  -> 512 px/CTA
#define WSTR   136     // bf16 row stride (272B): conflict-free ldmatrix

typedef unsigned long long ull;
typedef unsigned int u32;

// ---------------- persistent device scratch ----------------
__device__ float g_kv[BATCH * HEADS * HC * HC];                      // 16384 elems
__device__ __align__(16) __nv_bfloat16 g_wkv[2][256][WSTR];          // kv weights hi/lo
__device__ __align__(16) __nv_bfloat16 g_m1[BATCH][2][CHN][WSTR];    // fused M1 hi/lo
__device__ __align__(16) __nv_bfloat16 g_o2[2][CHN][WSTR];           // o2 hi/lo

// ---------------- helpers ----------------
static __device__ __forceinline__ ull fma2(ull a, ull b, ull c) {
    ull d;
    asm("fma.rn.f32x2 %0, %1, %2, %3;" : "=l"(d) : "l"(a), "l"(b), "l"(c));
    return d;
}
static __device__ __forceinline__ float2 unpack2(ull v) {
    float2 r;
    asm("mov.b64 {%0, %1}, %2;" : "=f"(r.x), "=f"(r.y) : "l"(v));
    return r;
}
static __device__ __forceinline__ float gelu_exact(float v) { return v * normcdff(v); }

static __device__ __forceinline__ u32 smem_u32(const void* p) {
    u32 a;
    asm("{ .reg .u64 t; cvta.to.shared.u64 t, %1; cvt.u32.u64 %0, t; }" : "=r"(a) : "l"(p));
    return a;
}

#define LDSM4(r0, r1, r2, r3, a)                                           \
    asm volatile("ldmatrix.sync.aligned.m8n8.x4.shared.b16 {%0,%1,%2,%3}, [%4];" \
        : "=r"(r0), "=r"(r1), "=r"(r2), "=r"(r3) : "r"(a))

static __device__ __forceinline__ void mma16816(float* d, const u32* a, const u32* b) {
    asm volatile(
        "mma.sync.aligned.m16n8k16.row.col.f32.bf16.bf16.f32 "
        "{%0,%1,%2,%3}, {%4,%5,%6,%7}, {%8,%9}, {%0,%1,%2,%3};"
        : "+f"(d[0]), "+f"(d[1]), "+f"(d[2]), "+f"(d[3])
        : "r"(a[0]), "r"(a[1]), "r"(a[2]), "r"(a[3]), "r"(b[0]), "r"(b[1]));
}

static __device__ __forceinline__ void split_bf16(float w, __nv_bfloat16& hi, __nv_bfloat16& lo) {
    hi = __float2bfloat16(w);
    lo = __float2bfloat16(w - __bfloat162float(hi));
}

// ============================================================================
__global__ void zero_kv_kernel() {
    int i = blockIdx.x * blockDim.x + threadIdx.x;
    if (i < BATCH * HEADS * HC * HC) g_kv[i] = 0.f;
}

// Split k/v weight rows to bf16 hi/lo, padded [o][WSTR].
__global__ void prep_wkv_kernel(const float* __restrict__ qkv_w) {
    int idx = blockIdx.x * blockDim.x + threadIdx.x;   // 32768
    int o = idx >> 7, c = idx & 127;
    int row = (o >> 5) * 48 + 16 + (o & 31);
    __nv_bfloat16 hi, lo;
    split_bf16(qkv_w[row * CHN + c], hi, lo);
    g_wkv[0][o][c] = hi;
    g_wkv[1][o][c] = lo;
}

// ============================================================================
// Kernel A: k,v = W_kv @ x  (mma.sync bf16, 3-term split), LN(16), kv outer.
// 512 threads = 16 warps: 8(M) x 2(N); warp tile 32 out x 16 px.
// x loads double-buffered through registers.
// ============================================================================
__global__ void __launch_bounds__(512, 1) kv_accum_kernel(
    const float* __restrict__ x,
    const float* __restrict__ klw, const float* __restrict__ klb,
    const float* __restrict__ vlw, const float* __restrict__ vlb)
{
    extern __shared__ __align__(16) unsigned char sm[];
    const int OFF_WH = 0;          // 256*WSTR*2 = 69632
    const int OFF_WL = 69632;
    const int OFF_XH = 139264;     // 32*WSTR*2 = 8704
    const int OFF_XL = 147968;
    const int OFF_LN = 156672;     // 256*34*4 = 34816
    const int OFF_LW = 191488;
    const int OFF_LB = 192512;     // total 193536

    const u32 sbase = smem_u32(sm);
    float* lnbuf = (float*)(sm + OFF_LN);
    float* lw = (float*)(sm + OFF_LW);
    float* lb = (float*)(sm + OFF_LB);

    const int tid = threadIdx.x;
    const int wid = tid >> 5, lane = tid & 31;
    const int b = blockIdx.y;
    const int n0 = blockIdx.x * (PXA * NCHA);

    {   // weight images -> smem (139264 B = 8704 float4 = 17*512)
        const float4* src = (const float4*)&g_wkv[0][0][0];
        float4* dst = (float4*)(sm + OFF_WH);
        #pragma unroll
        for (int i = 0; i < 17; i++) dst[tid + i * 512] = src[tid + i * 512];
    }
    if (tid < 256) {
        int o = tid, h = o >> 5, d = o & 15;
        if (o & 16) { lw[o] = vlw[h * HC + d]; lb[o] = vlb[h * HC + d]; }
        else        { lw[o] = klw[h * HC + d]; lb[o] = klb[h * HC + d]; }
    }

    // warp GEMM mapping
    const int wm = wid & 7, wn = wid >> 3;
    const int m_base = wm * 32, n_base = wn * 16;
    const int a_row = m_base + (lane & 15), a_col8 = (lane >> 4) * 8;
    const u32 aoff = (u32)(a_row * WSTR + a_col8) * 2;
    const int b_row = n_base + (lane & 7) + (lane >> 4) * 8;
    const int b_col8 = ((lane >> 3) & 1) * 8;
    const u32 boff = (u32)(b_row * WSTR + b_col8) * 2;

    // loader mapping: channel, 8-px segment
    const int lc = tid >> 2, lseg = (tid & 3) * 8;
    const float* gx_base = x + ((size_t)b * CHN + lc) * NPIX + lseg;
    // outer-product mapping
    const int ohead = wid & 7, ophalf = (wid >> 3) * 16;
    const int odd = lane >> 1, oe0 = (lane & 1) * 8;

    ull kvacc[8];
    #pragma unroll
    for (int t = 0; t < 8; t++) kvacc[t] = 0ull;

    // prefetch chunk 0
    float vv[8];
    {
        const float4* g = (const float4*)(gx_base + n0);
        float4 v0 = g[0], v1 = g[1];
        vv[0]=v0.x; vv[1]=v0.y; vv[2]=v0.z; vv[3]=v0.w;
        vv[4]=v1.x; vv[5]=v1.y; vv[6]=v1.z; vv[7]=v1.w;
    }

    for (int ch = 0; ch < NCHA; ch++) {
        __syncthreads();   // prev chunk fully consumed; weight copy visible

        {   // current chunk regs -> smem split
            __nv_bfloat16* xh = (__nv_bfloat16*)(sm + OFF_XH);
            __nv_bfloat16* xl = (__nv_bfloat16*)(sm + OFF_XL);
            #pragma unroll
            for (int j = 0; j < 8; j++) {
                __nv_bfloat16 hi, lo;
                split_bf16(vv[j], hi, lo);
                xh[(lseg + j) * WSTR + lc] = hi;
                xl[(lseg + j) * WSTR + lc] = lo;
            }
        }
        if (ch + 1 < NCHA) {   // prefetch next chunk (latency hidden by GEMM/LN)
            const float4* g = (const float4*)(gx_base + n0 + (ch + 1) * PXA);
            float4 v0 = g[0], v1 = g[1];
            vv[0]=v0.x; vv[1]=v0.y; vv[2]=v0.z; vv[3]=v0.w;
            vv[4]=v1.x; vv[5]=v1.y; vv[6]=v1.z; vv[7]=v1.w;
        }
        __syncthreads();

        // GEMM: 2 m16-tiles x 2 n8-tiles, K=128 in 8 steps, 3-term split
        float acc[2][2][4];
        #pragma unroll
        for (int i = 0; i < 2; i++)
            #pragma unroll
            for (int j = 0; j < 2; j++)
                #pragma unroll
                for (int q = 0; q < 4; q++) acc[i][j][q] = 0.f;

        #pragma unroll
        for (int ks = 0; ks < 8; ks++) {
            const u32 kk = ks * 32;
            u32 Ah[2][4], Al[2][4], Bh[4], Bl[4];
            LDSM4(Ah[0][0], Ah[0][1], Ah[0][2], Ah[0][3], sbase + OFF_WH + aoff + kk);
            LDSM4(Ah[1][0], Ah[1][1], Ah[1][2], Ah[1][3], sbase + OFF_WH + aoff + kk + 16 * WSTR * 2);
            LDSM4(Al[0][0], Al[0][1], Al[0][2], Al[0][3], sbase + OFF_WL + aoff + kk);
            LDSM4(Al[1][0], Al[1][1], Al[1][2], Al[1][3], sbase + OFF_WL + aoff + kk + 16 * WSTR * 2);
            LDSM4(Bh[0], Bh[1], Bh[2], Bh[3], sbase + OFF_XH + boff + kk);
            LDSM4(Bl[0], Bl[1], Bl[2], Bl[3], sbase + OFF_XL + boff + kk);
            #pragma unroll
            for (int i = 0; i < 2; i++) {
                #pragma unroll
                for (int j = 0; j < 2; j++) {
                    mma16816(acc[i][j], Ah[i], Bh + j * 2);
                    mma16816(acc[i][j], Al[i], Bh + j * 2);
                    mma16816(acc[i][j], Ah[i], Bl + j * 2);
                }
            }
        }

        // D -> lnbuf[out][px] (stride 34)
        #pragma unroll
        for (int i = 0; i < 2; i++) {
            #pragma unroll
            for (int j = 0; j < 2; j++) {
                int px = n_base + j * 8 + (lane & 3) * 2;
                int o0 = m_base + i * 16 + (lane >> 2);
                *(float2*)&lnbuf[o0 * 34 + px]       = make_float2(acc[i][j][0], acc[i][j][1]);
                *(float2*)&lnbuf[(o0 + 8) * 34 + px] = make_float2(acc[i][j][2], acc[i][j][3]);
            }
        }
        __syncthreads();

        {   // LayerNorm: 512 tasks = 32 px x 8 heads x {k,v}
            int p = tid & 31, hh = (tid >> 5) & 7, part = tid >> 8;
            int rbase = hh * 32 + part * 16;
            float t[16]; float s = 0.f;
            #pragma unroll
            for (int d = 0; d < 16; d++) { t[d] = lnbuf[(rbase + d) * 34 + p]; s += t[d]; }
            float m = s * (1.f / 16.f);
            float var = 0.f;
            #pragma unroll
            for (int d = 0; d < 16; d++) { float dv = t[d] - m; var += dv * dv; }
            float inv = 1.f / (sqrtf(var * (1.f / 15.f)) + EPS);
            #pragma unroll
            for (int d = 0; d < 16; d++)
                lnbuf[(rbase + d) * 34 + p] =
                    lw[rbase + d] * ((t[d] - m) * inv) + lb[rbase + d];
        }
        __syncthreads();

        {   // kv outer product (f32x2), 16 px per warp
            const float* kr = &lnbuf[(ohead * 32 + odd) * 34 + ophalf];
            #pragma unroll
            for (int p = 0; p < 16; p += 2) {
                ull k2 = *(const ull*)&kr[p];
                #pragma unroll
                for (int t = 0; t < 8; t++) {
                    ull v2 = *(const ull*)&lnbuf[(ohead * 32 + 16 + oe0 + t) * 34 + ophalf + p];
                    kvacc[t] = fma2(k2, v2, kvacc[t]);
                }
            }
        }
    }

    #pragma unroll
    for (int t = 0; t < 8; t++) {
        float2 v = unpack2(kvacc[t]);
        atomicAdd(&g_kv[((b * HEADS + ohead) * HC + odd) * HC + oe0 + t], v.x + v.y);
    }
}

// ============================================================================
// Kernel B: fold attention -> M1[b] = o1_w @ (A + I); emit bf16 hi/lo images.
// Parallel version: grid (16 slices x 8 batches); each block recomputes As
// in smem (cheap) and emits its 8-row slice of M1 (+ o2 slice on b==0).
// ============================================================================
__global__ void build_mats_kernel(const float* __restrict__ qkv_w,
                                  const float* __restrict__ o1_w,
                                  const float* __restrict__ o2_w)
{
    extern __shared__ float smf[];
    float* kvs = smf;           // 2048
    float* As  = smf + 2048;    // [128][129]
    const int tid = threadIdx.x;
    const int slice = blockIdx.x;   // 0..15 -> 8 M1 rows each
    const int b     = blockIdx.y;

    for (int i = tid; i < HEADS * HC * HC; i += 256)
        kvs[i] = g_kv[b * HEADS * HC * HC + i] * (1.f / NPIX);
    __syncthreads();

    // As[j][c] (full 128x128, recomputed per block; K=16 -> cheap)
    for (int idx = tid; idx < CHN * CHN; idx += 256) {
        int j = idx >> 7, c = idx & 127;
        int h = j >> 4, e = j & 15;
        float s = 0.f;
        #pragma unroll
        for (int d = 0; d < HC; d++)
            s += qkv_w[(h * 48 + d) * CHN + c] * kvs[(h * HC + d) * HC + e];
        As[j * 129 + c] = s;
    }
    __syncthreads();

    // M1 slice: rows [slice*8, slice*8+8)
    for (int idx = tid; idx < 8 * CHN; idx += 256) {
        int o = slice * 8 + (idx >> 7), c = idx & 127;
        float s = o1_w[o * CHN + c];   // identity term
        #pragma unroll 8
        for (int j = 0; j < CHN; j++)
            s += o1_w[o * CHN + j] * As[j * 129 + c];
        __nv_bfloat16 hi, lo;
        split_bf16(s, hi, lo);
        g_m1[b][0][o][c] = hi;
        g_m1[b][1][o][c] = lo;
    }
    if (b == 0) {
        for (int idx = tid; idx < 8 * CHN; idx += 256) {
            int o = slice * 8 + (idx >> 7), c = idx & 127;
            __nv_bfloat16 hi, lo;
            split_bf16(o2_w[o * CHN + c], hi, lo);
            g_o2[0][o][c] = hi;
            g_o2[1][o][c] = lo;
        }
    }
}

// ============================================================================
// Kernel C: out = gelu( o2 @ gelu( M1[b] @ x ) + x ), both GEMMs mma.sync.
// 512 threads = 16 warps: 4(M) x 4(N); warp tile 32 out x 16 px; chunk 64 px.
// x loads double-buffered through registers.
// ============================================================================
__global__ void __launch_bounds__(512, 1) mlp_kernel(
    const float* __restrict__ x, float* __restrict__ out)
{
    extern __shared__ __align__(16) unsigned char sm[];
    const int OFF_M1H = 0;          // 128*WSTR*2 = 34816
    const int OFF_M1L = 34816;
    const int OFF_O2H = 69632;
    const int OFF_O2L = 104448;
    const int OFF_XH  = 139264;     // 64*WSTR*2 = 17408
    const int OFF_XL  = 156672;
    const int OFF_UH  = 174080;
    const int OFF_UL  = 191488;     // total 208896

    const u32 sbase = smem_u32(sm);
    const int tid = threadIdx.x;
    const int wid = tid >> 5, lane = tid & 31;
    const int b = blockIdx.y;
    const int n0 = blockIdx.x * (PXC * NCHC);

    {   // weight images -> smem: 4352 float4 each pair
        const float4* s1 = (const float4*)&g_m1[b][0][0][0];
        const float4* s2 = (const float4*)&g_o2[0][0][0];
        float4* d1 = (float4*)(sm + OFF_M1H);
        float4* d2 = (float4*)(sm + OFF_O2H);
        #pragma unroll
        for (int i = 0; i < 8; i++) {
            d1[tid + i * 512] = s1[tid + i * 512];
            d2[tid + i * 512] = s2[tid + i * 512];
        }
        if (tid < 256) {
            d1[tid + 4096] = s1[tid + 4096];
            d2[tid + 4096] = s2[tid + 4096];
        }
    }

    const int wm = wid & 3, wn = wid >> 2;
    const int m_base = wm * 32, n_base = wn * 16;
    const u32 aoff = (u32)((m_base + (lane & 15)) * WSTR + (lane >> 4) * 8) * 2;
    const u32 boff = (u32)((n_base + (lane & 7) + (lane >> 4) * 8) * WSTR
                           + ((lane >> 3) & 1) * 8) * 2;

    const int lc = tid >> 2, lseg = (tid & 3) * 16;   // loader: channel, 16-px seg
    const float* gx_base = x + ((size_t)b * CHN + lc) * NPIX + lseg;

    // prefetch chunk 0
    float vv[16];
    {
        const float4* g = (const float4*)(gx_base + n0);
        #pragma unroll
        for (int q = 0; q < 4; q++) {
            float4 v = g[q];
            vv[q*4+0]=v.x; vv[q*4+1]=v.y; vv[q*4+2]=v.z; vv[q*4+3]=v.w;
        }
    }

    for (int ch = 0; ch < NCHC; ch++) {
        const int nb = n0 + ch * PXC;
        {   // current chunk regs -> smem split
            __nv_bfloat16* xh = (__nv_bfloat16*)(sm + OFF_XH);
            __nv_bfloat16* xl = (__nv_bfloat16*)(sm + OFF_XL);
            #pragma unroll
            for (int j = 0; j < 16; j++) {
                __nv_bfloat16 hi, lo;
                split_bf16(vv[j], hi, lo);
                xh[(lseg + j) * WSTR + lc] = hi;
                xl[(lseg + j) * WSTR + lc] = lo;
            }
        }
        if (ch + 1 < NCHC) {   // prefetch next chunk
            const float4* g = (const float4*)(gx_base + n0 + (ch + 1) * PXC);
            #pragma unroll
            for (int q = 0; q < 4; q++) {
                float4 v = g[q];
                vv[q*4+0]=v.x; vv[q*4+1]=v.y; vv[q*4+2]=v.z; vv[q*4+3]=v.w;
            }
        }
        __syncthreads();

        // ---- GEMM1: D1 = M1 @ x ----
        float a1[2][2][4];
        #pragma unroll
        for (int i = 0; i < 2; i++)
            #pragma unroll
            for (int j = 0; j < 2; j++)
                #pragma unroll
                for (int q = 0; q < 4; q++) a1[i][j][q] = 0.f;

        #pragma unroll
        for (int ks = 0; ks < 8; ks++) {
            const u32 kk = ks * 32;
            u32 Ah[2][4], Al[2][4], Bh[4], Bl[4];
            LDSM4(Ah[0][0], Ah[0][1], Ah[0][2], Ah[0][3], sbase + OFF_M1H + aoff + kk);
            LDSM4(Ah[1][0], Ah[1][1], Ah[1][2], Ah[1][3], sbase + OFF_M1H + aoff + kk + 16 * WSTR * 2);
            LDSM4(Al[0][0], Al[0][1], Al[0][2], Al[0][3], sbase + OFF_M1L + aoff + kk);
            LDSM4(Al[1][0], Al[1][1], Al[1][2], Al[1][3], sbase + OFF_M1L + aoff + kk + 16 * WSTR * 2);
            LDSM4(Bh[0], Bh[1], Bh[2], Bh[3], sbase + OFF_XH + boff + kk);
            LDSM4(Bl[0], Bl[1], Bl[2], Bl[3], sbase + OFF_XL + boff + kk);
            #pragma unroll
            for (int i = 0; i < 2; i++)
                #pragma unroll
                for (int j = 0; j < 2; j++) {
                    mma16816(a1[i][j], Ah[i], Bh + j * 2);
                    mma16816(a1[i][j], Al[i], Bh + j * 2);
                    mma16816(a1[i][j], Ah[i], Bl + j * 2);
                }
        }

        {   // epilogue1: u = gelu(D1), split, store transposed [px][chan]
            __nv_bfloat16* uh = (__nv_bfloat16*)(sm + OFF_UH);
            __nv_bfloat16* ul = (__nv_bfloat16*)(sm + OFF_UL);
            #pragma unroll
            for (int i = 0; i < 2; i++)
                #pragma unroll
                for (int j = 0; j < 2; j++) {
                    int px = n_base + j * 8 + (lane & 3) * 2;
                    int o0 = m_base + i * 16 + (lane >> 2);
                    #pragma unroll
                    for (int q = 0; q < 4; q++) {
                        int pp = px + (q & 1);
                        int oo = o0 + (q >> 1) * 8;
                        float u = gelu_exact(a1[i][j][q]);
                        __nv_bfloat16 hi, lo;
                        split_bf16(u, hi, lo);
                        uh[pp * WSTR + oo] = hi;
                        ul[pp * WSTR + oo] = lo;
                    }
                }
        }
        __syncthreads();

        // ---- GEMM2: D2 = o2 @ u ----
        float a2[2][2][4];
        #pragma unroll
        for (int i = 0; i < 2; i++)
            #pragma unroll
            for (int j = 0; j < 2; j++)
                #pragma unroll
                for (int q = 0; q < 4; q++) a2[i][j][q] = 0.f;

        #pragma unroll
        for (int ks = 0; ks < 8; ks++) {
            const u32 kk = ks * 32;
            u32 Ah[2][4], Al[2][4], Bh[4], Bl[4];
            LDSM4(Ah[0][0], Ah[0][1], Ah[0][2], Ah[0][3], sbase + OFF_O2H + aoff + kk);
            LDSM4(Ah[1][0], Ah[1][1], Ah[1][2], Ah[1][3], sbase + OFF_O2H + aoff + kk + 16 * WSTR * 2);
            LDSM4(Al[0][0], Al[0][1], Al[0][2], Al[0][3], sbase + OFF_O2L + aoff + kk);
            LDSM4(Al[1][0], Al[1][1], Al[1][2], Al[1][3], sbase + OFF_O2L + aoff + kk + 16 * WSTR * 2);
            LDSM4(Bh[0], Bh[1], Bh[2], Bh[3], sbase + OFF_UH + boff + kk);
            LDSM4(Bl[0], Bl[1], Bl[2], Bl[3], sbase + OFF_UL + boff + kk);
            #pragma unroll
            for (int i = 0; i < 2; i++)
                #pragma unroll
                for (int j = 0; j < 2; j++) {
                    mma16816(a2[i][j], Ah[i], Bh + j * 2);
                    mma16816(a2[i][j], Al[i], Bh + j * 2);
                    mma16816(a2[i][j], Ah[i], Bl + j * 2);
                }
        }

        {   // epilogue2: out = gelu(D2 + x), direct LDG/STG (float2)
            #pragma unroll
            for (int i = 0; i < 2; i++)
                #pragma unroll
                for (int j = 0; j < 2; j++) {
                    int px = nb + n_base + j * 8 + (lane & 3) * 2;
                    int o0 = m_base + i * 16 + (lane >> 2);
                    #pragma unroll
                    for (int half = 0; half < 2; half++) {
                        int oo = o0 + half * 8;
                        const float* xr = x + ((size_t)b * CHN + oo) * NPIX + px;
                        float* orow = out + ((size_t)b * CHN + oo) * NPIX + px;
                        float2 xv = *(const float2*)xr;
                        float2 r;
                        r.x = gelu_exact(a2[i][j][half * 2 + 0] + xv.x);
                        r.y = gelu_exact(a2[i][j][half * 2 + 1] + xv.y);
                        *(float2*)orow = r;
                    }
                }
        }
        __syncthreads();   // U/X consumers done before next chunk overwrites
    }
}

// ============================================================================
extern "C" void kernel_launch(void* const* d_in, const int* in_sizes, int n_in,
                              void* d_out, int out_size) {
    const float* x     = (const float*)d_in[0];
    const float* qkv_w = (const float*)d_in[1];
    const float* o1_w  = (const float*)d_in[2];
    const float* o2_w  = (const float*)d_in[3];
    const float* klw   = (const float*)d_in[4];
    const float* klb   = (const float*)d_in[5];
    const float* vlw   = (const float*)d_in[6];
    const float* vlb   = (const float*)d_in[7];
    float* out = (float*)d_out;

    const int SMEM_A = 193536;
    const int SMEM_B = (2048 + 128 * 129) * (int)sizeof(float);
    const int SMEM_C = 208896;

    cudaFuncSetAttribute(kv_accum_kernel,   cudaFuncAttributeMaxDynamicSharedMemorySize, SMEM_A);
    cudaFuncSetAttribute(build_mats_kernel, cudaFuncAttributeMaxDynamicSharedMemorySize, SMEM_B);
    cudaFuncSetAttribute(mlp_kernel,        cudaFuncAttributeMaxDynamicSharedMemorySize, SMEM_C);

    zero_kv_kernel<<<32, 512>>>();
    prep_wkv_kernel<<<64, 512>>>(qkv_w);
    kv_accum_kernel<<<dim3(NPIX / (PXA * NCHA), BATCH), 512, SMEM_A>>>(
        x, klw, klb, vlw, vlb);
    build_mats_kernel<<<dim3(16, BATCH), 256, SMEM_B>>>(qkv_w, o1_w, o2_w);
    mlp_kernel<<<dim3(NPIX / (PXC * NCHC), BATCH), 512, SMEM_C>>>(x, out);
}

// round 8
// speedup vs baseline: 3.3498x; 1.0091x over previous
#include <cuda_runtime.h>
#include <cuda_bf16.h>
#include <math.h>
#include <stdint.h>

#define BATCH  8
#define CHN    128
#define HEADS  8
#define HC     16
#define NPIX   65536
#define EPS    1e-5f

#define PXA    64      // kernel A pixels per chunk
#define NCHA   8       // chunks per CTA (A)  -> 512 px/CTA
#define PXC    128     // kernel C pixels per chunk
#define NCHC   4       // chunks per CTA (C)  -> 512 px/CTA
#define WSTR   136     // bf16 row stride (272B): conflict-free ldmatrix
#define LNS    66      // LN buffer row stride (floats)

typedef unsigned long long ull;
typedef unsigned int u32;

// ---------------- persistent device scratch ----------------
__device__ float g_kv[BATCH * HEADS * HC * HC];                      // 16384 elems
__device__ __align__(16) __nv_bfloat16 g_wkv[2][256][WSTR];          // kv weights hi/lo
__device__ __align__(16) __nv_bfloat16 g_m1[BATCH][2][CHN][WSTR];    // fused M1 hi/lo
__device__ __align__(16) __nv_bfloat16 g_o2[2][CHN][WSTR];           // o2 hi/lo

// ---------------- helpers ----------------
static __device__ __forceinline__ ull fma2(ull a, ull b, ull c) {
    ull d;
    asm("fma.rn.f32x2 %0, %1, %2, %3;" : "=l"(d) : "l"(a), "l"(b), "l"(c));
    return d;
}
static __device__ __forceinline__ float2 unpack2(ull v) {
    float2 r;
    asm("mov.b64 {%0, %1}, %2;" : "=f"(r.x), "=f"(r.y) : "l"(v));
    return r;
}
static __device__ __forceinline__ float gelu_exact(float v) { return v * normcdff(v); }

static __device__ __forceinline__ u32 smem_u32(const void* p) {
    u32 a;
    asm("{ .reg .u64 t; cvta.to.shared.u64 t, %1; cvt.u32.u64 %0, t; }" : "=r"(a) : "l"(p));
    return a;
}

#define LDSM4(r0, r1, r2, r3, a)                                           \
    asm volatile("ldmatrix.sync.aligned.m8n8.x4.shared.b16 {%0,%1,%2,%3}, [%4];" \
        : "=r"(r0), "=r"(r1), "=r"(r2), "=r"(r3) : "r"(a))

static __device__ __forceinline__ void mma16816(float* d, const u32* a, const u32* b) {
    asm volatile(
        "mma.sync.aligned.m16n8k16.row.col.f32.bf16.bf16.f32 "
        "{%0,%1,%2,%3}, {%4,%5,%6,%7}, {%8,%9}, {%0,%1,%2,%3};"
        : "+f"(d[0]), "+f"(d[1]), "+f"(d[2]), "+f"(d[3])
        : "r"(a[0]), "r"(a[1]), "r"(a[2]), "r"(a[3]), "r"(b[0]), "r"(b[1]));
}

static __device__ __forceinline__ void split_bf16(float w, __nv_bfloat16& hi, __nv_bfloat16& lo) {
    hi = __float2bfloat16(w);
    lo = __float2bfloat16(w - __bfloat162float(hi));
}

// ============================================================================
__global__ void zero_kv_kernel() {
    int i = blockIdx.x * blockDim.x + threadIdx.x;
    if (i < BATCH * HEADS * HC * HC) g_kv[i] = 0.f;
}

__global__ void prep_wkv_kernel(const float* __restrict__ qkv_w) {
    int idx = blockIdx.x * blockDim.x + threadIdx.x;   // 32768
    int o = idx >> 7, c = idx & 127;
    int row = (o >> 5) * 48 + 16 + (o & 31);
    __nv_bfloat16 hi, lo;
    split_bf16(qkv_w[row * CHN + c], hi, lo);
    g_wkv[0][o][c] = hi;
    g_wkv[1][o][c] = lo;
}

// ============================================================================
// Kernel A: k,v = W_kv @ x  (mma.sync bf16, 3-term split), LN(16), kv outer.
// 512 threads = 16 warps: 8(M) x 2(N); warp tile 32 out x 32 px; chunk 64 px.
// LN buffer overlays the dead X region.
// ============================================================================
__global__ void __launch_bounds__(512, 1) kv_accum_kernel(
    const float* __restrict__ x,
    const float* __restrict__ klw, const float* __restrict__ klb,
    const float* __restrict__ vlw, const float* __restrict__ vlb)
{
    extern __shared__ __align__(16) unsigned char sm[];
    const int OFF_WH = 0;          // 69632
    const int OFF_WL = 69632;      // weights end 139264
    const int OFF_XH = 139264;     // 64*WSTR*2 = 17408
    const int OFF_XL = 156672;     // X end 174080
    const int OFF_LN = 139264;     // overlay: 256*LNS*4 = 67584, ends 206848
    const int OFF_LW = 206848;
    const int OFF_LB = 207872;     // total 208896

    const u32 sbase = smem_u32(sm);
    float* lnbuf = (float*)(sm + OFF_LN);
    float* lw = (float*)(sm + OFF_LW);
    float* lb = (float*)(sm + OFF_LB);

    const int tid = threadIdx.x;
    const int wid = tid >> 5, lane = tid & 31;
    const int b = blockIdx.y;
    const int n0 = blockIdx.x * (PXA * NCHA);

    {   // weight images -> smem (8704 float4 = 17*512)
        const float4* src = (const float4*)&g_wkv[0][0][0];
        float4* dst = (float4*)(sm + OFF_WH);
        #pragma unroll
        for (int i = 0; i < 17; i++) dst[tid + i * 512] = src[tid + i * 512];
    }
    if (tid < 256) {
        int o = tid, h = o >> 5, d = o & 15;
        if (o & 16) { lw[o] = vlw[h * HC + d]; lb[o] = vlb[h * HC + d]; }
        else        { lw[o] = klw[h * HC + d]; lb[o] = klb[h * HC + d]; }
    }

    // warp GEMM mapping: 8(M) x 2(N), warp tile 32 out x 32 px
    const int wm = wid & 7, wn = wid >> 3;
    const int m_base = wm * 32, n_base = wn * 32;
    const u32 aoff = (u32)((m_base + (lane & 15)) * WSTR + (lane >> 4) * 8) * 2;
    const u32 boff = (u32)((n_base + (lane & 7) + (lane >> 4) * 8) * WSTR
                           + ((lane >> 3) & 1) * 8) * 2;

    // loader mapping: channel, 16-px segment
    const int lc = tid >> 2, lseg = (tid & 3) * 16;
    const float* gx_base = x + ((size_t)b * CHN + lc) * NPIX + lseg;
    // outer-product mapping
    const int ohead = wid & 7, ophalf = (wid >> 3) * 32;
    const int odd = lane >> 1, oe0 = (lane & 1) * 8;

    ull kvacc[8];
    #pragma unroll
    for (int t = 0; t < 8; t++) kvacc[t] = 0ull;

    // prefetch chunk 0
    float vv[16];
    {
        const float4* g = (const float4*)(gx_base + n0);
        #pragma unroll
        for (int q = 0; q < 4; q++) {
            float4 v = g[q];
            vv[q*4+0]=v.x; vv[q*4+1]=v.y; vv[q*4+2]=v.z; vv[q*4+3]=v.w;
        }
    }

    for (int ch = 0; ch < NCHA; ch++) {
        __syncthreads();   // lnbuf consumers done (outer product); weights visible

        {   // current chunk regs -> X split (overwrites lnbuf region)
            __nv_bfloat16* xh = (__nv_bfloat16*)(sm + OFF_XH);
            __nv_bfloat16* xl = (__nv_bfloat16*)(sm + OFF_XL);
            #pragma unroll
            for (int j = 0; j < 16; j++) {
                __nv_bfloat16 hi, lo;
                split_bf16(vv[j], hi, lo);
                xh[(lseg + j) * WSTR + lc] = hi;
                xl[(lseg + j) * WSTR + lc] = lo;
            }
        }
        if (ch + 1 < NCHA) {   // prefetch next chunk
            const float4* g = (const float4*)(gx_base + n0 + (ch + 1) * PXA);
            #pragma unroll
            for (int q = 0; q < 4; q++) {
                float4 v = g[q];
                vv[q*4+0]=v.x; vv[q*4+1]=v.y; vv[q*4+2]=v.z; vv[q*4+3]=v.w;
            }
        }
        __syncthreads();

        // GEMM: 2 m16 x 4 n8 tiles, K=128 in 8 steps, 3-term split
        float acc[2][4][4];
        #pragma unroll
        for (int i = 0; i < 2; i++)
            #pragma unroll
            for (int j = 0; j < 4; j++)
                #pragma unroll
                for (int q = 0; q < 4; q++) acc[i][j][q] = 0.f;

        #pragma unroll
        for (int ks = 0; ks < 8; ks++) {
            const u32 kk = ks * 32;
            u32 Ah[2][4], Al[2][4], Bh[8], Bl[8];
            LDSM4(Ah[0][0], Ah[0][1], Ah[0][2], Ah[0][3], sbase + OFF_WH + aoff + kk);
            LDSM4(Ah[1][0], Ah[1][1], Ah[1][2], Ah[1][3], sbase + OFF_WH + aoff + kk + 16 * WSTR * 2);
            LDSM4(Al[0][0], Al[0][1], Al[0][2], Al[0][3], sbase + OFF_WL + aoff + kk);
            LDSM4(Al[1][0], Al[1][1], Al[1][2], Al[1][3], sbase + OFF_WL + aoff + kk + 16 * WSTR * 2);
            LDSM4(Bh[0], Bh[1], Bh[2], Bh[3], sbase + OFF_XH + boff + kk);
            LDSM4(Bh[4], Bh[5], Bh[6], Bh[7], sbase + OFF_XH + boff + kk + 16 * WSTR * 2);
            LDSM4(Bl[0], Bl[1], Bl[2], Bl[3], sbase + OFF_XL + boff + kk);
            LDSM4(Bl[4], Bl[5], Bl[6], Bl[7], sbase + OFF_XL + boff + kk + 16 * WSTR * 2);
            #pragma unroll
            for (int i = 0; i < 2; i++) {
                #pragma unroll
                for (int j = 0; j < 4; j++) {
                    mma16816(acc[i][j], Ah[i], Bh + j * 2);
                    mma16816(acc[i][j], Al[i], Bh + j * 2);
                    mma16816(acc[i][j], Ah[i], Bl + j * 2);
                }
            }
        }
        __syncthreads();   // X reads done -> lnbuf overlay is safe to write

        // D -> lnbuf[out][px] (stride LNS)
        #pragma unroll
        for (int i = 0; i < 2; i++) {
            #pragma unroll
            for (int j = 0; j < 4; j++) {
                int px = n_base + j * 8 + (lane & 3) * 2;
                int o0 = m_base + i * 16 + (lane >> 2);
                *(float2*)&lnbuf[o0 * LNS + px]       = make_float2(acc[i][j][0], acc[i][j][1]);
                *(float2*)&lnbuf[(o0 + 8) * LNS + px] = make_float2(acc[i][j][2], acc[i][j][3]);
            }
        }
        __syncthreads();

        {   // LayerNorm: 1024 tasks = 64 px x 8 heads x {k,v}; 2 per thread
            int p = tid & 63, hh = (tid >> 6) & 7;
            #pragma unroll
            for (int part = 0; part < 2; part++) {
                int rbase = hh * 32 + part * 16;
                float t[16]; float s = 0.f;
                #pragma unroll
                for (int d = 0; d < 16; d++) { t[d] = lnbuf[(rbase + d) * LNS + p]; s += t[d]; }
                float m = s * (1.f / 16.f);
                float var = 0.f;
                #pragma unroll
                for (int d = 0; d < 16; d++) { float dv = t[d] - m; var += dv * dv; }
                float inv = 1.f / (sqrtf(var * (1.f / 15.f)) + EPS);
                #pragma unroll
                for (int d = 0; d < 16; d++)
                    lnbuf[(rbase + d) * LNS + p] =
                        lw[rbase + d] * ((t[d] - m) * inv) + lb[rbase + d];
            }
        }
        __syncthreads();

        {   // kv outer product (f32x2), 32 px per warp
            const float* kr = &lnbuf[(ohead * 32 + odd) * LNS + ophalf];
            #pragma unroll
            for (int p = 0; p < 32; p += 2) {
                ull k2 = *(const ull*)&kr[p];
                #pragma unroll
                for (int t = 0; t < 8; t++) {
                    ull v2 = *(const ull*)&lnbuf[(ohead * 32 + 16 + oe0 + t) * LNS + ophalf + p];
                    kvacc[t] = fma2(k2, v2, kvacc[t]);
                }
            }
        }
    }

    #pragma unroll
    for (int t = 0; t < 8; t++) {
        float2 v = unpack2(kvacc[t]);
        atomicAdd(&g_kv[((b * HEADS + ohead) * HC + odd) * HC + oe0 + t], v.x + v.y);
    }
}

// ============================================================================
// Kernel B: fold attention -> M1[b] = o1_w @ (A + I); emit bf16 hi/lo images.
// grid (16 slices x 8 batches), 512 threads.
// ============================================================================
__global__ void build_mats_kernel(const float* __restrict__ qkv_w,
                                  const float* __restrict__ o1_w,
                                  const float* __restrict__ o2_w)
{
    extern __shared__ float smf[];
    float* kvs = smf;           // 2048
    float* As  = smf + 2048;    // [128][129]
    const int tid = threadIdx.x;
    const int slice = blockIdx.x;   // 0..15 -> 8 M1 rows each
    const int b     = blockIdx.y;

    for (int i = tid; i < HEADS * HC * HC; i += 512)
        kvs[i] = g_kv[b * HEADS * HC * HC + i] * (1.f / NPIX);
    __syncthreads();

    for (int idx = tid; idx < CHN * CHN; idx += 512) {
        int j = idx >> 7, c = idx & 127;
        int h = j >> 4, e = j & 15;
        float s = 0.f;
        #pragma unroll
        for (int d = 0; d < HC; d++)
            s += qkv_w[(h * 48 + d) * CHN + c] * kvs[(h * HC + d) * HC + e];
        As[j * 129 + c] = s;
    }
    __syncthreads();

    for (int idx = tid; idx < 8 * CHN; idx += 512) {
        int o = slice * 8 + (idx >> 7), c = idx & 127;
        float s = o1_w[o * CHN + c];   // identity term
        #pragma unroll 8
        for (int j = 0; j < CHN; j++)
            s += o1_w[o * CHN + j] * As[j * 129 + c];
        __nv_bfloat16 hi, lo;
        split_bf16(s, hi, lo);
        g_m1[b][0][o][c] = hi;
        g_m1[b][1][o][c] = lo;
    }
    if (b == 0) {
        for (int idx = tid; idx < 8 * CHN; idx += 512) {
            int o = slice * 8 + (idx >> 7), c = idx & 127;
            __nv_bfloat16 hi, lo;
            split_bf16(o2_w[o * CHN + c], hi, lo);
            g_o2[0][o][c] = hi;
            g_o2[1][o][c] = lo;
        }
    }
}

// ============================================================================
// Kernel C: out = gelu( o2 @ gelu( M1[b] @ x ) + x ), both GEMMs mma.sync.
// 512 threads = 16 warps: 4(M) x 4(N); warp tile 32 out x 32 px; chunk 128 px.
// U images overlay the dead X region.
// ============================================================================
__global__ void __launch_bounds__(512, 1) mlp_kernel(
    const float* __restrict__ x, float* __restrict__ out)
{
    extern __shared__ __align__(16) unsigned char sm[];
    const int OFF_M1H = 0;          // 34816
    const int OFF_M1L = 34816;
    const int OFF_O2H = 69632;
    const int OFF_O2L = 104448;     // weights end 139264
    const int OFF_XH  = 139264;     // 128*WSTR*2 = 34816
    const int OFF_XL  = 174080;     // X end 208896
    const int OFF_UH  = 139264;     // overlay on X
    const int OFF_UL  = 174080;     // total 208896

    const u32 sbase = smem_u32(sm);
    const int tid = threadIdx.x;
    const int wid = tid >> 5, lane = tid & 31;
    const int b = blockIdx.y;
    const int n0 = blockIdx.x * (PXC * NCHC);

    {   // weight images -> smem: 4352 float4 each pair
        const float4* s1 = (const float4*)&g_m1[b][0][0][0];
        const float4* s2 = (const float4*)&g_o2[0][0][0];
        float4* d1 = (float4*)(sm + OFF_M1H);
        float4* d2 = (float4*)(sm + OFF_O2H);
        #pragma unroll
        for (int i = 0; i < 8; i++) {
            d1[tid + i * 512] = s1[tid + i * 512];
            d2[tid + i * 512] = s2[tid + i * 512];
        }
        if (tid < 256) {
            d1[tid + 4096] = s1[tid + 4096];
            d2[tid + 4096] = s2[tid + 4096];
        }
    }

    // warp mapping: 4(M) x 4(N), warp tile 32 out x 32 px
    const int wm = wid & 3, wn = wid >> 2;
    const int m_base = wm * 32, n_base = wn * 32;
    const u32 aoff = (u32)((m_base + (lane & 15)) * WSTR + (lane >> 4) * 8) * 2;
    const u32 boff = (u32)((n_base + (lane & 7) + (lane >> 4) * 8) * WSTR
                           + ((lane >> 3) & 1) * 8) * 2;

    const int lc = tid >> 2, lseg = (tid & 3) * 32;   // loader: channel, 32-px seg
    const float* gx_base = x + ((size_t)b * CHN + lc) * NPIX + lseg;

    // prefetch chunk 0
    float vv[32];
    {
        const float4* g = (const float4*)(gx_base + n0);
        #pragma unroll
        for (int q = 0; q < 8; q++) {
            float4 v = g[q];
            vv[q*4+0]=v.x; vv[q*4+1]=v.y; vv[q*4+2]=v.z; vv[q*4+3]=v.w;
        }
    }

    for (int ch = 0; ch < NCHC; ch++) {
        const int nb = n0 + ch * PXC;
        {   // current chunk regs -> X split (overwrites U region; safe: GEMM2 done)
            __nv_bfloat16* xh = (__nv_bfloat16*)(sm + OFF_XH);
            __nv_bfloat16* xl = (__nv_bfloat16*)(sm + OFF_XL);
            #pragma unroll
            for (int j = 0; j < 32; j++) {
                __nv_bfloat16 hi, lo;
                split_bf16(vv[j], hi, lo);
                xh[(lseg + j) * WSTR + lc] = hi;
                xl[(lseg + j) * WSTR + lc] = lo;
            }
        }
        if (ch + 1 < NCHC) {   // prefetch next chunk
            const float4* g = (const float4*)(gx_base + n0 + (ch + 1) * PXC);
            #pragma unroll
            for (int q = 0; q < 8; q++) {
                float4 v = g[q];
                vv[q*4+0]=v.x; vv[q*4+1]=v.y; vv[q*4+2]=v.z; vv[q*4+3]=v.w;
            }
        }
        __syncthreads();

        // ---- GEMM1: D1 = M1 @ x ----
        float a1[2][4][4];
        #pragma unroll
        for (int i = 0; i < 2; i++)
            #pragma unroll
            for (int j = 0; j < 4; j++)
                #pragma unroll
                for (int q = 0; q < 4; q++) a1[i][j][q] = 0.f;

        #pragma unroll
        for (int ks = 0; ks < 8; ks++) {
            const u32 kk = ks * 32;
            u32 Ah[2][4], Al[2][4], Bh[8], Bl[8];
            LDSM4(Ah[0][0], Ah[0][1], Ah[0][2], Ah[0][3], sbase + OFF_M1H + aoff + kk);
            LDSM4(Ah[1][0], Ah[1][1], Ah[1][2], Ah[1][3], sbase + OFF_M1H + aoff + kk + 16 * WSTR * 2);
            LDSM4(Al[0][0], Al[0][1], Al[0][2], Al[0][3], sbase + OFF_M1L + aoff + kk);
            LDSM4(Al[1][0], Al[1][1], Al[1][2], Al[1][3], sbase + OFF_M1L + aoff + kk + 16 * WSTR * 2);
            LDSM4(Bh[0], Bh[1], Bh[2], Bh[3], sbase + OFF_XH + boff + kk);
            LDSM4(Bh[4], Bh[5], Bh[6], Bh[7], sbase + OFF_XH + boff + kk + 16 * WSTR * 2);
            LDSM4(Bl[0], Bl[1], Bl[2], Bl[3], sbase + OFF_XL + boff + kk);
            LDSM4(Bl[4], Bl[5], Bl[6], Bl[7], sbase + OFF_XL + boff + kk + 16 * WSTR * 2);
            #pragma unroll
            for (int i = 0; i < 2; i++)
                #pragma unroll
                for (int j = 0; j < 4; j++) {
                    mma16816(a1[i][j], Ah[i], Bh + j * 2);
                    mma16816(a1[i][j], Al[i], Bh + j * 2);
                    mma16816(a1[i][j], Ah[i], Bl + j * 2);
                }
        }
        __syncthreads();   // X reads done -> U overlay safe

        {   // epilogue1: u = gelu(D1), split, store transposed [px][chan] over X
            __nv_bfloat16* uh = (__nv_bfloat16*)(sm + OFF_UH);
            __nv_bfloat16* ul = (__nv_bfloat16*)(sm + OFF_UL);
            #pragma unroll
            for (int i = 0; i < 2; i++)
                #pragma unroll
                for (int j = 0; j < 4; j++) {
                    int px = n_base + j * 8 + (lane & 3) * 2;
                    int o0 = m_base + i * 16 + (lane >> 2);
                    #pragma unroll
                    for (int q = 0; q < 4; q++) {
                        int pp = px + (q & 1);
                        int oo = o0 + (q >> 1) * 8;
                        float u = gelu_exact(a1[i][j][q]);
                        __nv_bfloat16 hi, lo;
                        split_bf16(u, hi, lo);
                        uh[pp * WSTR + oo] = hi;
                        ul[pp * WSTR + oo] = lo;
                    }
                }
        }
        __syncthreads();

        // ---- GEMM2: D2 = o2 @ u ----
        float a2[2][4][4];
        #pragma unroll
        for (int i = 0; i < 2; i++)
            #pragma unroll
            for (int j = 0; j < 4; j++)
                #pragma unroll
                for (int q = 0; q < 4; q++) a2[i][j][q] = 0.f;

        #pragma unroll
        for (int ks = 0; ks < 8; ks++) {
            const u32 kk = ks * 32;
            u32 Ah[2][4], Al[2][4], Bh[8], Bl[8];
            LDSM4(Ah[0][0], Ah[0][1], Ah[0][2], Ah[0][3], sbase + OFF_O2H + aoff + kk);
            LDSM4(Ah[1][0], Ah[1][1], Ah[1][2], Ah[1][3], sbase + OFF_O2H + aoff + kk + 16 * WSTR * 2);
            LDSM4(Al[0][0], Al[0][1], Al[0][2], Al[0][3], sbase + OFF_O2L + aoff + kk);
            LDSM4(Al[1][0], Al[1][1], Al[1][2], Al[1][3], sbase + OFF_O2L + aoff + kk + 16 * WSTR * 2);
            LDSM4(Bh[0], Bh[1], Bh[2], Bh[3], sbase + OFF_UH + boff + kk);
            LDSM4(Bh[4], Bh[5], Bh[6], Bh[7], sbase + OFF_UH + boff + kk + 16 * WSTR * 2);
            LDSM4(Bl[0], Bl[1], Bl[2], Bl[3], sbase + OFF_UL + boff + kk);
            LDSM4(Bl[4], Bl[5], Bl[6], Bl[7], sbase + OFF_UL + boff + kk + 16 * WSTR * 2);
            #pragma unroll
            for (int i = 0; i < 2; i++)
                #pragma unroll
                for (int j = 0; j < 4; j++) {
                    mma16816(a2[i][j], Ah[i], Bh + j * 2);
                    mma16816(a2[i][j], Al[i], Bh + j * 2);
                    mma16816(a2[i][j], Ah[i], Bl + j * 2);
                }
        }

        {   // epilogue2: out = gelu(D2 + x), direct LDG/STG (float2)
            #pragma unroll
            for (int i = 0; i < 2; i++)
                #pragma unroll
                for (int j = 0; j < 4; j++) {
                    int px = nb + n_base + j * 8 + (lane & 3) * 2;
                    int o0 = m_base + i * 16 + (lane >> 2);
                    #pragma unroll
                    for (int half = 0; half < 2; half++) {
                        int oo = o0 + half * 8;
                        const float* xr = x + ((size_t)b * CHN + oo) * NPIX + px;
                        float* orow = out + ((size_t)b * CHN + oo) * NPIX + px;
                        float2 xv = *(const float2*)xr;
                        float2 r;
                        r.x = gelu_exact(a2[i][j][half * 2 + 0] + xv.x);
                        r.y = gelu_exact(a2[i][j][half * 2 + 1] + xv.y);
                        *(float2*)orow = r;
                    }
                }
        }
        __syncthreads();   // U reads (GEMM2) done before next chunk's X write
    }
}

// ============================================================================
extern "C" void kernel_launch(void* const* d_in, const int* in_sizes, int n_in,
                              void* d_out, int out_size) {
    const float* x     = (const float*)d_in[0];
    const float* qkv_w = (const float*)d_in[1];
    const float* o1_w  = (const float*)d_in[2];
    const float* o2_w  = (const float*)d_in[3];
    const float* klw   = (const float*)d_in[4];
    const float* klb   = (const float*)d_in[5];
    const float* vlw   = (const float*)d_in[6];
    const float* vlb   = (const float*)d_in[7];
    float* out = (float*)d_out;

    const int SMEM_A = 208896;
    const int SMEM_B = (2048 + 128 * 129) * (int)sizeof(float);
    const int SMEM_C = 208896;

    cudaFuncSetAttribute(kv_accum_kernel,   cudaFuncAttributeMaxDynamicSharedMemorySize, SMEM_A);
    cudaFuncSetAttribute(build_mats_kernel, cudaFuncAttributeMaxDynamicSharedMemorySize, SMEM_B);
    cudaFuncSetAttribute(mlp_kernel,        cudaFuncAttributeMaxDynamicSharedMemorySize, SMEM_C);

    zero_kv_kernel<<<32, 512>>>();
    prep_wkv_kernel<<<64, 512>>>(qkv_w);
    kv_accum_kernel<<<dim3(NPIX / (PXA * NCHA), BATCH), 512, SMEM_A>>>(
        x, klw, klb, vlw, vlb);
    build_mats_kernel<<<dim3(16, BATCH), 512, SMEM_B>>>(qkv_w, o1_w, o2_w);
    mlp_kernel<<<dim3(NPIX / (PXC * NCHC), BATCH), 512, SMEM_C>>>(x, out);
}

// round 10
// speedup vs baseline: 3.8816x; 1.1588x over previous
#include <cuda_runtime.h>
#include <cuda_bf16.h>
#include <math.h>
#include <stdint.h>

#define BATCH  8
#define CHN    128
#define HEADS  8
#define HC     16
#define NPIX   65536
#define EPS    1e-5f

#define PXA    64      // kernel A pixels per chunk
#define NCHA   8       // chunks per CTA (A)  -> 512 px/CTA
#define PXC    128     // kernel C pixels per chunk
#define NCHC   4       // chunks per CTA (C)  -> 512 px/CTA
#define WSTR   136     // bf16 row stride (272B): conflict-free ldmatrix
#define LNS    66      // LN buffer row stride (floats)

typedef unsigned long long ull;
typedef unsigned int u32;

// ---------------- persistent device scratch ----------------
__device__ float g_kv[BATCH * HEADS * HC * HC];                      // 16384 elems
__device__ __align__(16) __nv_bfloat16 g_wkv[2][256][WSTR];          // kv weights hi/lo
__device__ __align__(16) __nv_bfloat16 g_m1[BATCH][2][CHN][WSTR];    // fused M1 hi/lo
__device__ __align__(16) __nv_bfloat16 g_o2[2][CHN][WSTR];           // o2 hi/lo

// ---------------- helpers ----------------
static __device__ __forceinline__ ull fma2(ull a, ull b, ull c) {
    ull d;
    asm("fma.rn.f32x2 %0, %1, %2, %3;" : "=l"(d) : "l"(a), "l"(b), "l"(c));
    return d;
}
static __device__ __forceinline__ float2 unpack2(ull v) {
    float2 r;
    asm("mov.b64 {%0, %1}, %2;" : "=f"(r.x), "=f"(r.y) : "l"(v));
    return r;
}
// fast gelu: 0.5*v*(1+tanh(0.79788456*(v + 0.044715*v^3))), HW tanh.approx
static __device__ __forceinline__ float gelu_fast(float v) {
    float c = v * v;
    float t = v * (0.79788456f + 0.035677408f * c);
    float th;
    asm("tanh.approx.f32 %0, %1;" : "=f"(th) : "f"(t));
    return 0.5f * v * (1.f + th);
}
static __device__ __forceinline__ float sqrt_approx(float v) {
    float r;
    asm("sqrt.approx.f32 %0, %1;" : "=f"(r) : "f"(v));
    return r;
}
static __device__ __forceinline__ float rcp_approx(float v) {
    float r;
    asm("rcp.approx.f32 %0, %1;" : "=f"(r) : "f"(v));
    return r;
}

static __device__ __forceinline__ u32 smem_u32(const void* p) {
    u32 a;
    asm("{ .reg .u64 t; cvta.to.shared.u64 t, %1; cvt.u32.u64 %0, t; }" : "=r"(a) : "l"(p));
    return a;
}

#define LDSM4(r0, r1, r2, r3, a)                                           \
    asm volatile("ldmatrix.sync.aligned.m8n8.x4.shared.b16 {%0,%1,%2,%3}, [%4];" \
        : "=r"(r0), "=r"(r1), "=r"(r2), "=r"(r3) : "r"(a))

static __device__ __forceinline__ void mma16816(float* d, const u32* a, const u32* b) {
    asm volatile(
        "mma.sync.aligned.m16n8k16.row.col.f32.bf16.bf16.f32 "
        "{%0,%1,%2,%3}, {%4,%5,%6,%7}, {%8,%9}, {%0,%1,%2,%3};"
        : "+f"(d[0]), "+f"(d[1]), "+f"(d[2]), "+f"(d[3])
        : "r"(a[0]), "r"(a[1]), "r"(a[2]), "r"(a[3]), "r"(b[0]), "r"(b[1]));
}

static __device__ __forceinline__ void split_bf16(float w, __nv_bfloat16& hi, __nv_bfloat16& lo) {
    hi = __float2bfloat16(w);
    lo = __float2bfloat16(w - __bfloat162float(hi));
}

// ============================================================================
__global__ void zero_kv_kernel() {
    int i = blockIdx.x * blockDim.x + threadIdx.x;
    if (i < BATCH * HEADS * HC * HC) g_kv[i] = 0.f;
}

__global__ void prep_wkv_kernel(const float* __restrict__ qkv_w) {
    int idx = blockIdx.x * blockDim.x + threadIdx.x;   // 32768
    int o = idx >> 7, c = idx & 127;
    int row = (o >> 5) * 48 + 16 + (o & 31);
    __nv_bfloat16 hi, lo;
    split_bf16(qkv_w[row * CHN + c], hi, lo);
    g_wkv[0][o][c] = hi;
    g_wkv[1][o][c] = lo;
}

// ============================================================================
// Kernel A: k,v = W_kv @ x  (mma.sync bf16, 3-term split), LN(16), kv outer.
// 512 threads = 16 warps: 8(M) x 2(N); warp tile 32 out x 32 px; chunk 64 px.
// ============================================================================
__global__ void __launch_bounds__(512, 1) kv_accum_kernel(
    const float* __restrict__ x,
    const float* __restrict__ klw, const float* __restrict__ klb,
    const float* __restrict__ vlw, const float* __restrict__ vlb)
{
    extern __shared__ __align__(16) unsigned char sm[];
    const int OFF_WH = 0;          // 69632
    const int OFF_WL = 69632;      // weights end 139264
    const int OFF_XH = 139264;     // 64*WSTR*2 = 17408
    const int OFF_XL = 156672;     // X end 174080
    const int OFF_LN = 139264;     // overlay: 256*LNS*4 = 67584, ends 206848
    const int OFF_LW = 206848;
    const int OFF_LB = 207872;     // total 208896

    const u32 sbase = smem_u32(sm);
    float* lnbuf = (float*)(sm + OFF_LN);
    float* lw = (float*)(sm + OFF_LW);
    float* lb = (float*)(sm + OFF_LB);

    const int tid = threadIdx.x;
    const int wid = tid >> 5, lane = tid & 31;
    const int b = blockIdx.y;
    const int n0 = blockIdx.x * (PXA * NCHA);

    {   // weight images -> smem (8704 float4 = 17*512)
        const float4* src = (const float4*)&g_wkv[0][0][0];
        float4* dst = (float4*)(sm + OFF_WH);
        #pragma unroll
        for (int i = 0; i < 17; i++) dst[tid + i * 512] = src[tid + i * 512];
    }
    if (tid < 256) {
        int o = tid, h = o >> 5, d = o & 15;
        if (o & 16) { lw[o] = vlw[h * HC + d]; lb[o] = vlb[h * HC + d]; }
        else        { lw[o] = klw[h * HC + d]; lb[o] = klb[h * HC + d]; }
    }

    // warp GEMM mapping: 8(M) x 2(N), warp tile 32 out x 32 px
    const int wm = wid & 7, wn = wid >> 3;
    const int m_base = wm * 32, n_base = wn * 32;
    const u32 aoff = (u32)((m_base + (lane & 15)) * WSTR + (lane >> 4) * 8) * 2;
    const u32 boff = (u32)((n_base + (lane & 7) + (lane >> 4) * 8) * WSTR
                           + ((lane >> 3) & 1) * 8) * 2;

    // loader mapping: channel, 16-px segment
    const int lc = tid >> 2, lseg = (tid & 3) * 16;
    const float* gx_base = x + ((size_t)b * CHN + lc) * NPIX + lseg;
    // outer-product mapping
    const int ohead = wid & 7, ophalf = (wid >> 3) * 32;
    const int odd = lane >> 1, oe0 = (lane & 1) * 8;

    ull kvacc[8];
    #pragma unroll
    for (int t = 0; t < 8; t++) kvacc[t] = 0ull;

    // prefetch chunk 0
    float vv[16];
    {
        const float4* g = (const float4*)(gx_base + n0);
        #pragma unroll
        for (int q = 0; q < 4; q++) {
            float4 v = g[q];
            vv[q*4+0]=v.x; vv[q*4+1]=v.y; vv[q*4+2]=v.z; vv[q*4+3]=v.w;
        }
    }

    for (int ch = 0; ch < NCHA; ch++) {
        __syncthreads();   // lnbuf consumers done (outer product); weights visible

        {   // current chunk regs -> X split (overwrites lnbuf region)
            __nv_bfloat16* xh = (__nv_bfloat16*)(sm + OFF_XH);
            __nv_bfloat16* xl = (__nv_bfloat16*)(sm + OFF_XL);
            #pragma unroll
            for (int j = 0; j < 16; j++) {
                __nv_bfloat16 hi, lo;
                split_bf16(vv[j], hi, lo);
                xh[(lseg + j) * WSTR + lc] = hi;
                xl[(lseg + j) * WSTR + lc] = lo;
            }
        }
        if (ch + 1 < NCHA) {   // prefetch next chunk
            const float4* g = (const float4*)(gx_base + n0 + (ch + 1) * PXA);
            #pragma unroll
            for (int q = 0; q < 4; q++) {
                float4 v = g[q];
                vv[q*4+0]=v.x; vv[q*4+1]=v.y; vv[q*4+2]=v.z; vv[q*4+3]=v.w;
            }
        }
        __syncthreads();

        // GEMM: 2 m16 x 4 n8 tiles, K=128 in 8 steps, 3-term split
        float acc[2][4][4];
        #pragma unroll
        for (int i = 0; i < 2; i++)
            #pragma unroll
            for (int j = 0; j < 4; j++)
                #pragma unroll
                for (int q = 0; q < 4; q++) acc[i][j][q] = 0.f;

        #pragma unroll
        for (int ks = 0; ks < 8; ks++) {
            const u32 kk = ks * 32;
            u32 Ah[2][4], Al[2][4], Bh[8], Bl[8];
            LDSM4(Ah[0][0], Ah[0][1], Ah[0][2], Ah[0][3], sbase + OFF_WH + aoff + kk);
            LDSM4(Ah[1][0], Ah[1][1], Ah[1][2], Ah[1][3], sbase + OFF_WH + aoff + kk + 16 * WSTR * 2);
            LDSM4(Al[0][0], Al[0][1], Al[0][2], Al[0][3], sbase + OFF_WL + aoff + kk);
            LDSM4(Al[1][0], Al[1][1], Al[1][2], Al[1][3], sbase + OFF_WL + aoff + kk + 16 * WSTR * 2);
            LDSM4(Bh[0], Bh[1], Bh[2], Bh[3], sbase + OFF_XH + boff + kk);
            LDSM4(Bh[4], Bh[5], Bh[6], Bh[7], sbase + OFF_XH + boff + kk + 16 * WSTR * 2);
            LDSM4(Bl[0], Bl[1], Bl[2], Bl[3], sbase + OFF_XL + boff + kk);
            LDSM4(Bl[4], Bl[5], Bl[6], Bl[7], sbase + OFF_XL + boff + kk + 16 * WSTR * 2);
            #pragma unroll
            for (int i = 0; i < 2; i++) {
                #pragma unroll
                for (int j = 0; j < 4; j++) {
                    mma16816(acc[i][j], Ah[i], Bh + j * 2);
                    mma16816(acc[i][j], Al[i], Bh + j * 2);
                    mma16816(acc[i][j], Ah[i], Bl + j * 2);
                }
            }
        }
        __syncthreads();   // X reads done -> lnbuf overlay is safe to write

        // D -> lnbuf[out][px] (stride LNS)
        #pragma unroll
        for (int i = 0; i < 2; i++) {
            #pragma unroll
            for (int j = 0; j < 4; j++) {
                int px = n_base + j * 8 + (lane & 3) * 2;
                int o0 = m_base + i * 16 + (lane >> 2);
                *(float2*)&lnbuf[o0 * LNS + px]       = make_float2(acc[i][j][0], acc[i][j][1]);
                *(float2*)&lnbuf[(o0 + 8) * LNS + px] = make_float2(acc[i][j][2], acc[i][j][3]);
            }
        }
        __syncthreads();

        {   // LayerNorm: 1024 tasks = 64 px x 8 heads x {k,v}; 2 per thread
            int p = tid & 63, hh = (tid >> 6) & 7;
            #pragma unroll
            for (int part = 0; part < 2; part++) {
                int rbase = hh * 32 + part * 16;
                float t[16]; float s = 0.f;
                #pragma unroll
                for (int d = 0; d < 16; d++) { t[d] = lnbuf[(rbase + d) * LNS + p]; s += t[d]; }
                float m = s * (1.f / 16.f);
                float var = 0.f;
                #pragma unroll
                for (int d = 0; d < 16; d++) { float dv = t[d] - m; var += dv * dv; }
                float inv = rcp_approx(sqrt_approx(var * (1.f / 15.f)) + EPS);
                #pragma unroll
                for (int d = 0; d < 16; d++)
                    lnbuf[(rbase + d) * LNS + p] =
                        lw[rbase + d] * ((t[d] - m) * inv) + lb[rbase + d];
            }
        }
        __syncthreads();

        {   // kv outer product (f32x2), 32 px per warp
            const float* kr = &lnbuf[(ohead * 32 + odd) * LNS + ophalf];
            #pragma unroll
            for (int p = 0; p < 32; p += 2) {
                ull k2 = *(const ull*)&kr[p];
                #pragma unroll
                for (int t = 0; t < 8; t++) {
                    ull v2 = *(const ull*)&lnbuf[(ohead * 32 + 16 + oe0 + t) * LNS + ophalf + p];
                    kvacc[t] = fma2(k2, v2, kvacc[t]);
                }
            }
        }
    }

    #pragma unroll
    for (int t = 0; t < 8; t++) {
        float2 v = unpack2(kvacc[t]);
        atomicAdd(&g_kv[((b * HEADS + ohead) * HC + odd) * HC + oe0 + t], v.x + v.y);
    }
}

// ============================================================================
// Kernel B: fold attention -> M1[b] = o1_w @ (A + I); emit bf16 hi/lo images.
// ============================================================================
__global__ void build_mats_kernel(const float* __restrict__ qkv_w,
                                  const float* __restrict__ o1_w,
                                  const float* __restrict__ o2_w)
{
    extern __shared__ float smf[];
    float* kvs = smf;           // 2048
    float* As  = smf + 2048;    // [128][129]
    const int tid = threadIdx.x;
    const int slice = blockIdx.x;   // 0..15 -> 8 M1 rows each
    const int b     = blockIdx.y;

    for (int i = tid; i < HEADS * HC * HC; i += 512)
        kvs[i] = g_kv[b * HEADS * HC * HC + i] * (1.f / NPIX);
    __syncthreads();

    for (int idx = tid; idx < CHN * CHN; idx += 512) {
        int j = idx >> 7, c = idx & 127;
        int h = j >> 4, e = j & 15;
        float s = 0.f;
        #pragma unroll
        for (int d = 0; d < HC; d++)
            s += qkv_w[(h * 48 + d) * CHN + c] * kvs[(h * HC + d) * HC + e];
        As[j * 129 + c] = s;
    }
    __syncthreads();

    for (int idx = tid; idx < 8 * CHN; idx += 512) {
        int o = slice * 8 + (idx >> 7), c = idx & 127;
        float s = o1_w[o * CHN + c];   // identity term
        #pragma unroll 8
        for (int j = 0; j < CHN; j++)
            s += o1_w[o * CHN + j] * As[j * 129 + c];
        __nv_bfloat16 hi, lo;
        split_bf16(s, hi, lo);
        g_m1[b][0][o][c] = hi;
        g_m1[b][1][o][c] = lo;
    }
    if (b == 0) {
        for (int idx = tid; idx < 8 * CHN; idx += 512) {
            int o = slice * 8 + (idx >> 7), c = idx & 127;
            __nv_bfloat16 hi, lo;
            split_bf16(o2_w[o * CHN + c], hi, lo);
            g_o2[0][o][c] = hi;
            g_o2[1][o][c] = lo;
        }
    }
}

// ============================================================================
// Kernel C: out = gelu( o2 @ gelu( M1[b] @ x ) + x ), both GEMMs mma.sync.
// 512 threads = 16 warps: 4(M) x 4(N); warp tile 32 out x 32 px; chunk 128 px.
// ============================================================================
__global__ void __launch_bounds__(512, 1) mlp_kernel(
    const float* __restrict__ x, float* __restrict__ out)
{
    extern __shared__ __align__(16) unsigned char sm[];
    const int OFF_M1H = 0;          // 34816
    const int OFF_M1L = 34816;
    const int OFF_O2H = 69632;
    const int OFF_O2L = 104448;     // weights end 139264
    const int OFF_XH  = 139264;     // 128*WSTR*2 = 34816
    const int OFF_XL  = 174080;     // X end 208896
    const int OFF_UH  = 139264;     // overlay on X
    const int OFF_UL  = 174080;     // total 208896

    const u32 sbase = smem_u32(sm);
    const int tid = threadIdx.x;
    const int wid = tid >> 5, lane = tid & 31;
    const int b = blockIdx.y;
    const int n0 = blockIdx.x * (PXC * NCHC);

    {   // weight images -> smem: 4352 float4 each pair
        const float4* s1 = (const float4*)&g_m1[b][0][0][0];
        const float4* s2 = (const float4*)&g_o2[0][0][0];
        float4* d1 = (float4*)(sm + OFF_M1H);
        float4* d2 = (float4*)(sm + OFF_O2H);
        #pragma unroll
        for (int i = 0; i < 8; i++) {
            d1[tid + i * 512] = s1[tid + i * 512];
            d2[tid + i * 512] = s2[tid + i * 512];
        }
        if (tid < 256) {
            d1[tid + 4096] = s1[tid + 4096];
            d2[tid + 4096] = s2[tid + 4096];
        }
    }

    // warp mapping: 4(M) x 4(N), warp tile 32 out x 32 px
    const int wm = wid & 3, wn = wid >> 2;
    const int m_base = wm * 32, n_base = wn * 32;
    const u32 aoff = (u32)((m_base + (lane & 15)) * WSTR + (lane >> 4) * 8) * 2;
    const u32 boff = (u32)((n_base + (lane & 7) + (lane >> 4) * 8) * WSTR
                           + ((lane >> 3) & 1) * 8) * 2;

    const int lc = tid >> 2, lseg = (tid & 3) * 32;   // loader: channel, 32-px seg
    const float* gx_base = x + ((size_t)b * CHN + lc) * NPIX + lseg;

    // prefetch chunk 0
    float vv[32];
    {
        const float4* g = (const float4*)(gx_base + n0);
        #pragma unroll
        for (int q = 0; q < 8; q++) {
            float4 v = g[q];
            vv[q*4+0]=v.x; vv[q*4+1]=v.y; vv[q*4+2]=v.z; vv[q*4+3]=v.w;
        }
    }

    for (int ch = 0; ch < NCHC; ch++) {
        const int nb = n0 + ch * PXC;
        {   // current chunk regs -> X split (overwrites U region; safe: GEMM2 done)
            __nv_bfloat16* xh = (__nv_bfloat16*)(sm + OFF_XH);
            __nv_bfloat16* xl = (__nv_bfloat16*)(sm + OFF_XL);
            #pragma unroll
            for (int j = 0; j < 32; j++) {
                __nv_bfloat16 hi, lo;
                split_bf16(vv[j], hi, lo);
                xh[(lseg + j) * WSTR + lc] = hi;
                xl[(lseg + j) * WSTR + lc] = lo;
            }
        }
        if (ch + 1 < NCHC) {   // prefetch next chunk
            const float4* g = (const float4*)(gx_base + n0 + (ch + 1) * PXC);
            #pragma unroll
            for (int q = 0; q < 8; q++) {
                float4 v = g[q];
                vv[q*4+0]=v.x; vv[q*4+1]=v.y; vv[q*4+2]=v.z; vv[q*4+3]=v.w;
            }
        }
        __syncthreads();

        // ---- GEMM1: D1 = M1 @ x ----
        float a1[2][4][4];
        #pragma unroll
        for (int i = 0; i < 2; i++)
            #pragma unroll
            for (int j = 0; j < 4; j++)
                #pragma unroll
                for (int q = 0; q < 4; q++) a1[i][j][q] = 0.f;

        #pragma unroll
        for (int ks = 0; ks < 8; ks++) {
            const u32 kk = ks * 32;
            u32 Ah[2][4], Al[2][4], Bh[8], Bl[8];
            LDSM4(Ah[0][0], Ah[0][1], Ah[0][2], Ah[0][3], sbase + OFF_M1H + aoff + kk);
            LDSM4(Ah[1][0], Ah[1][1], Ah[1][2], Ah[1][3], sbase + OFF_M1H + aoff + kk + 16 * WSTR * 2);
            LDSM4(Al[0][0], Al[0][1], Al[0][2], Al[0][3], sbase + OFF_M1L + aoff + kk);
            LDSM4(Al[1][0], Al[1][1], Al[1][2], Al[1][3], sbase + OFF_M1L + aoff + kk + 16 * WSTR * 2);
            LDSM4(Bh[0], Bh[1], Bh[2], Bh[3], sbase + OFF_XH + boff + kk);
            LDSM4(Bh[4], Bh[5], Bh[6], Bh[7], sbase + OFF_XH + boff + kk + 16 * WSTR * 2);
            LDSM4(Bl[0], Bl[1], Bl[2], Bl[3], sbase + OFF_XL + boff + kk);
            LDSM4(Bl[4], Bl[5], Bl[6], Bl[7], sbase + OFF_XL + boff + kk + 16 * WSTR * 2);
            #pragma unroll
            for (int i = 0; i < 2; i++)
                #pragma unroll
                for (int j = 0; j < 4; j++) {
                    mma16816(a1[i][j], Ah[i], Bh + j * 2);
                    mma16816(a1[i][j], Al[i], Bh + j * 2);
                    mma16816(a1[i][j], Ah[i], Bl + j * 2);
                }
        }
        __syncthreads();   // X reads done -> U overlay safe

        {   // epilogue1: u = gelu(D1), split, store transposed [px][chan] over X
            __nv_bfloat16* uh = (__nv_bfloat16*)(sm + OFF_UH);
            __nv_bfloat16* ul = (__nv_bfloat16*)(sm + OFF_UL);
            #pragma unroll
            for (int i = 0; i < 2; i++)
                #pragma unroll
                for (int j = 0; j < 4; j++) {
                    int px = n_base + j * 8 + (lane & 3) * 2;
                    int o0 = m_base + i * 16 + (lane >> 2);
                    #pragma unroll
                    for (int q = 0; q < 4; q++) {
                        int pp = px + (q & 1);
                        int oo = o0 + (q >> 1) * 8;
                        float u = gelu_fast(a1[i][j][q]);
                        __nv_bfloat16 hi, lo;
                        split_bf16(u, hi, lo);
                        uh[pp * WSTR + oo] = hi;
                        ul[pp * WSTR + oo] = lo;
                    }
                }
        }
        __syncthreads();

        // ---- GEMM2: D2 = o2 @ u ----
        float a2[2][4][4];
        #pragma unroll
        for (int i = 0; i < 2; i++)
            #pragma unroll
            for (int j = 0; j < 4; j++)
                #pragma unroll
                for (int q = 0; q < 4; q++) a2[i][j][q] = 0.f;

        #pragma unroll
        for (int ks = 0; ks < 8; ks++) {
            const u32 kk = ks * 32;
            u32 Ah[2][4], Al[2][4], Bh[8], Bl[8];
            LDSM4(Ah[0][0], Ah[0][1], Ah[0][2], Ah[0][3], sbase + OFF_O2H + aoff + kk);
            LDSM4(Ah[1][0], Ah[1][1], Ah[1][2], Ah[1][3], sbase + OFF_O2H + aoff + kk + 16 * WSTR * 2);
            LDSM4(Al[0][0], Al[0][1], Al[0][2], Al[0][3], sbase + OFF_O2L + aoff + kk);
            LDSM4(Al[1][0], Al[1][1], Al[1][2], Al[1][3], sbase + OFF_O2L + aoff + kk + 16 * WSTR * 2);
            LDSM4(Bh[0], Bh[1], Bh[2], Bh[3], sbase + OFF_UH + boff + kk);
            LDSM4(Bh[4], Bh[5], Bh[6], Bh[7], sbase + OFF_UH + boff + kk + 16 * WSTR * 2);
            LDSM4(Bl[0], Bl[1], Bl[2], Bl[3], sbase + OFF_UL + boff + kk);
            LDSM4(Bl[4], Bl[5], Bl[6], Bl[7], sbase + OFF_UL + boff + kk + 16 * WSTR * 2);
            #pragma unroll
            for (int i = 0; i < 2; i++)
                #pragma unroll
                for (int j = 0; j < 4; j++) {
                    mma16816(a2[i][j], Ah[i], Bh + j * 2);
                    mma16816(a2[i][j], Al[i], Bh + j * 2);
                    mma16816(a2[i][j], Ah[i], Bl + j * 2);
                }
        }

        {   // epilogue2: out = gelu(D2 + x), direct LDG/STG (float2)
            #pragma unroll
            for (int i = 0; i < 2; i++)
                #pragma unroll
                for (int j = 0; j < 4; j++) {
                    int px = nb + n_base + j * 8 + (lane & 3) * 2;
                    int o0 = m_base + i * 16 + (lane >> 2);
                    #pragma unroll
                    for (int half = 0; half < 2; half++) {
                        int oo = o0 + half * 8;
                        const float* xr = x + ((size_t)b * CHN + oo) * NPIX + px;
                        float* orow = out + ((size_t)b * CHN + oo) * NPIX + px;
                        float2 xv = *(const float2*)xr;
                        float2 r;
                        r.x = gelu_fast(a2[i][j][half * 2 + 0] + xv.x);
                        r.y = gelu_fast(a2[i][j][half * 2 + 1] + xv.y);
                        *(float2*)orow = r;
                    }
                }
        }
        __syncthreads();   // U reads (GEMM2) done before next chunk's X write
    }
}

// ============================================================================
extern "C" void kernel_launch(void* const* d_in, const int* in_sizes, int n_in,
                              void* d_out, int out_size) {
    const float* x     = (const float*)d_in[0];
    const float* qkv_w = (const float*)d_in[1];
    const float* o1_w  = (const float*)d_in[2];
    const float* o2_w  = (const float*)d_in[3];
    const float* klw   = (const float*)d_in[4];
    const float* klb   = (const float*)d_in[5];
    const float* vlw   = (const float*)d_in[6];
    const float* vlb   = (const float*)d_in[7];
    float* out = (float*)d_out;

    const int SMEM_A = 208896;
    const int SMEM_B = (2048 + 128 * 129) * (int)sizeof(float);
    const int SMEM_C = 208896;

    cudaFuncSetAttribute(kv_accum_kernel,   cudaFuncAttributeMaxDynamicSharedMemorySize, SMEM_A);
    cudaFuncSetAttribute(build_mats_kernel, cudaFuncAttributeMaxDynamicSharedMemorySize, SMEM_B);
    cudaFuncSetAttribute(mlp_kernel,        cudaFuncAttributeMaxDynamicSharedMemorySize, SMEM_C);

    zero_kv_kernel<<<32, 512>>>();
    prep_wkv_kernel<<<64, 512>>>(qkv_w);
    kv_accum_kernel<<<dim3(NPIX / (PXA * NCHA), BATCH), 512, SMEM_A>>>(
        x, klw, klb, vlw, vlb);
    build_mats_kernel<<<dim3(16, BATCH), 512, SMEM_B>>>(qkv_w, o1_w, o2_w);
    mlp_kernel<<<dim3(NPIX / (PXC * NCHC), BATCH), 512, SMEM_C>>>(x, out);
}

// round 11
// speedup vs baseline: 3.9616x; 1.0206x over previous
#include <cuda_runtime.h>
#include <cuda_bf16.h>
#include <math.h>
#include <stdint.h>

#define BATCH  8
#define CHN    128
#define HEADS  8
#define HC     16
#define NPIX   65536
#define EPS    1e-5f

#define PXA    64      // kernel A pixels per chunk
#define NCHA   8       // chunks per CTA (A)  -> 512 px/CTA
#define PXC    64      // kernel C pixels per chunk
#define NCHC   8       // chunks per CTA (C)  -> 512 px/CTA
#define WSTR   136     // bf16 row stride (272B): conflict-free ldmatrix
#define LNS    66      // LN buffer row stride (floats)

typedef unsigned long long ull;
typedef unsigned int u32;
typedef unsigned short u16;

// ---------------- persistent device scratch ----------------
__device__ float g_kv[BATCH * HEADS * HC * HC];                      // 16384 elems
__device__ __align__(16) __nv_bfloat16 g_wkv[2][256][WSTR];          // kv weights hi/lo
__device__ __align__(16) __nv_bfloat16 g_m1[BATCH][2][CHN][WSTR];    // fused M1 hi/lo
__device__ __align__(16) __nv_bfloat16 g_o2[2][CHN][WSTR];           // o2 hi/lo

// ---------------- helpers ----------------
static __device__ __forceinline__ ull fma2(ull a, ull b, ull c) {
    ull d;
    asm("fma.rn.f32x2 %0, %1, %2, %3;" : "=l"(d) : "l"(a), "l"(b), "l"(c));
    return d;
}
static __device__ __forceinline__ float2 unpack2(ull v) {
    float2 r;
    asm("mov.b64 {%0, %1}, %2;" : "=f"(r.x), "=f"(r.y) : "l"(v));
    return r;
}
// fast gelu: 0.5*v*(1+tanh(0.79788456*(v + 0.044715*v^3))), HW tanh.approx
static __device__ __forceinline__ float gelu_fast(float v) {
    float c = v * v;
    float t = v * (0.79788456f + 0.035677408f * c);
    float th;
    asm("tanh.approx.f32 %0, %1;" : "=f"(th) : "f"(t));
    return 0.5f * v * (1.f + th);
}
static __device__ __forceinline__ float sqrt_approx(float v) {
    float r;
    asm("sqrt.approx.f32 %0, %1;" : "=f"(r) : "f"(v));
    return r;
}
static __device__ __forceinline__ float rcp_approx(float v) {
    float r;
    asm("rcp.approx.f32 %0, %1;" : "=f"(r) : "f"(v));
    return r;
}
// pack two floats to bf16x2: result = {upper: a_hi, lower: a_lo}
static __device__ __forceinline__ u32 pack_bf16x2(float a_hi, float a_lo) {
    u32 r;
    asm("cvt.rn.bf16x2.f32 %0, %1, %2;" : "=r"(r) : "f"(a_hi), "f"(a_lo));
    return r;
}

static __device__ __forceinline__ u32 smem_u32(const void* p) {
    u32 a;
    asm("{ .reg .u64 t; cvta.to.shared.u64 t, %1; cvt.u32.u64 %0, t; }" : "=r"(a) : "l"(p));
    return a;
}

#define LDSM4(r0, r1, r2, r3, a)                                           \
    asm volatile("ldmatrix.sync.aligned.m8n8.x4.shared.b16 {%0,%1,%2,%3}, [%4];" \
        : "=r"(r0), "=r"(r1), "=r"(r2), "=r"(r3) : "r"(a))

static __device__ __forceinline__ void mma16816(float* d, const u32* a, const u32* b) {
    asm volatile(
        "mma.sync.aligned.m16n8k16.row.col.f32.bf16.bf16.f32 "
        "{%0,%1,%2,%3}, {%4,%5,%6,%7}, {%8,%9}, {%0,%1,%2,%3};"
        : "+f"(d[0]), "+f"(d[1]), "+f"(d[2]), "+f"(d[3])
        : "r"(a[0]), "r"(a[1]), "r"(a[2]), "r"(a[3]), "r"(b[0]), "r"(b[1]));
}

static __device__ __forceinline__ void split_bf16(float w, __nv_bfloat16& hi, __nv_bfloat16& lo) {
    hi = __float2bfloat16(w);
    lo = __float2bfloat16(w - __bfloat162float(hi));
}

// packed split of a channel pair (v0 = chan c, v1 = chan c+1) -> hi/lo bf16x2 words
static __device__ __forceinline__ void split_pair(float v0, float v1, u32& h2, u32& l2) {
    h2 = pack_bf16x2(v1, v0);
    float h0 = __uint_as_float(h2 << 16);
    float h1 = __uint_as_float(h2 & 0xFFFF0000u);
    l2 = pack_bf16x2(v1 - h1, v0 - h0);
}

// ============================================================================
__global__ void zero_kv_kernel() {
    int i = blockIdx.x * blockDim.x + threadIdx.x;
    if (i < BATCH * HEADS * HC * HC) g_kv[i] = 0.f;
}

__global__ void prep_wkv_kernel(const float* __restrict__ qkv_w) {
    int idx = blockIdx.x * blockDim.x + threadIdx.x;   // 32768
    int o = idx >> 7, c = idx & 127;
    int row = (o >> 5) * 48 + 16 + (o & 31);
    __nv_bfloat16 hi, lo;
    split_bf16(qkv_w[row * CHN + c], hi, lo);
    g_wkv[0][o][c] = hi;
    g_wkv[1][o][c] = lo;
}

// ============================================================================
// Kernel A: k,v = W_kv @ x  (mma.sync bf16, 3-term split), LN(16), kv outer.
// 512 threads = 16 warps: 8(M) x 2(N); warp tile 32 out x 32 px; chunk 64 px.
// ============================================================================
__global__ void __launch_bounds__(512, 1) kv_accum_kernel(
    const float* __restrict__ x,
    const float* __restrict__ klw, const float* __restrict__ klb,
    const float* __restrict__ vlw, const float* __restrict__ vlb)
{
    extern __shared__ __align__(16) unsigned char sm[];
    const int OFF_WH = 0;          // 69632
    const int OFF_WL = 69632;      // weights end 139264
    const int OFF_XH = 139264;     // 64*WSTR*2 = 17408
    const int OFF_XL = 156672;     // X end 174080
    const int OFF_LN = 139264;     // overlay: 256*LNS*4 = 67584, ends 206848
    const int OFF_LW = 206848;
    const int OFF_LB = 207872;     // total 208896

    const u32 sbase = smem_u32(sm);
    float* lnbuf = (float*)(sm + OFF_LN);
    float* lw = (float*)(sm + OFF_LW);
    float* lb = (float*)(sm + OFF_LB);

    const int tid = threadIdx.x;
    const int wid = tid >> 5, lane = tid & 31;
    const int b = blockIdx.y;
    const int n0 = blockIdx.x * (PXA * NCHA);

    {   // weight images -> smem (8704 float4 = 17*512)
        const float4* src = (const float4*)&g_wkv[0][0][0];
        float4* dst = (float4*)(sm + OFF_WH);
        #pragma unroll
        for (int i = 0; i < 17; i++) dst[tid + i * 512] = src[tid + i * 512];
    }
    if (tid < 256) {
        int o = tid, h = o >> 5, d = o & 15;
        if (o & 16) { lw[o] = vlw[h * HC + d]; lb[o] = vlb[h * HC + d]; }
        else        { lw[o] = klw[h * HC + d]; lb[o] = klb[h * HC + d]; }
    }

    // warp GEMM mapping: 8(M) x 2(N), warp tile 32 out x 32 px
    const int wm = wid & 7, wn = wid >> 3;
    const int m_base = wm * 32, n_base = wn * 32;
    const u32 aoff = (u32)((m_base + (lane & 15)) * WSTR + (lane >> 4) * 8) * 2;
    const u32 boff = (u32)((n_base + (lane & 7) + (lane >> 4) * 8) * WSTR
                           + ((lane >> 3) & 1) * 8) * 2;

    // loader mapping: 2 adjacent channels x 8 px per thread
    const int lc2 = (tid & 63) * 2, lpx = (tid >> 6) * 8;
    const float* gx0 = x + ((size_t)b * CHN + lc2) * NPIX + lpx;
    const float* gx1 = gx0 + NPIX;
    // outer-product mapping
    const int ohead = wid & 7, ophalf = (wid >> 3) * 32;
    const int odd = lane >> 1, oe0 = (lane & 1) * 8;

    ull kvacc[8];
    #pragma unroll
    for (int t = 0; t < 8; t++) kvacc[t] = 0ull;

    // prefetch chunk 0
    float vv0[8], vv1[8];
    {
        const float4* g0 = (const float4*)(gx0 + n0);
        const float4* g1 = (const float4*)(gx1 + n0);
        float4 a0 = g0[0], a1 = g0[1], c0 = g1[0], c1 = g1[1];
        vv0[0]=a0.x; vv0[1]=a0.y; vv0[2]=a0.z; vv0[3]=a0.w;
        vv0[4]=a1.x; vv0[5]=a1.y; vv0[6]=a1.z; vv0[7]=a1.w;
        vv1[0]=c0.x; vv1[1]=c0.y; vv1[2]=c0.z; vv1[3]=c0.w;
        vv1[4]=c1.x; vv1[5]=c1.y; vv1[6]=c1.z; vv1[7]=c1.w;
    }

    for (int ch = 0; ch < NCHA; ch++) {
        __syncthreads();   // lnbuf consumers done (outer product); weights visible

        {   // current chunk regs -> X split (packed 4B stores)
            #pragma unroll
            for (int j = 0; j < 8; j++) {
                u32 h2, l2;
                split_pair(vv0[j], vv1[j], h2, l2);
                int boffj = ((lpx + j) * WSTR + lc2) * 2;
                *(u32*)(sm + OFF_XH + boffj) = h2;
                *(u32*)(sm + OFF_XL + boffj) = l2;
            }
        }
        if (ch + 1 < NCHA) {   // prefetch next chunk
            const float4* g0 = (const float4*)(gx0 + n0 + (ch + 1) * PXA);
            const float4* g1 = (const float4*)(gx1 + n0 + (ch + 1) * PXA);
            float4 a0 = g0[0], a1 = g0[1], c0 = g1[0], c1 = g1[1];
            vv0[0]=a0.x; vv0[1]=a0.y; vv0[2]=a0.z; vv0[3]=a0.w;
            vv0[4]=a1.x; vv0[5]=a1.y; vv0[6]=a1.z; vv0[7]=a1.w;
            vv1[0]=c0.x; vv1[1]=c0.y; vv1[2]=c0.z; vv1[3]=c0.w;
            vv1[4]=c1.x; vv1[5]=c1.y; vv1[6]=c1.z; vv1[7]=c1.w;
        }
        __syncthreads();

        // GEMM: 2 m16 x 4 n8 tiles, K=128 in 8 steps, 3-term split
        float acc[2][4][4];
        #pragma unroll
        for (int i = 0; i < 2; i++)
            #pragma unroll
            for (int j = 0; j < 4; j++)
                #pragma unroll
                for (int q = 0; q < 4; q++) acc[i][j][q] = 0.f;

        #pragma unroll
        for (int ks = 0; ks < 8; ks++) {
            const u32 kk = ks * 32;
            u32 Ah[2][4], Al[2][4], Bh[8], Bl[8];
            LDSM4(Ah[0][0], Ah[0][1], Ah[0][2], Ah[0][3], sbase + OFF_WH + aoff + kk);
            LDSM4(Ah[1][0], Ah[1][1], Ah[1][2], Ah[1][3], sbase + OFF_WH + aoff + kk + 16 * WSTR * 2);
            LDSM4(Al[0][0], Al[0][1], Al[0][2], Al[0][3], sbase + OFF_WL + aoff + kk);
            LDSM4(Al[1][0], Al[1][1], Al[1][2], Al[1][3], sbase + OFF_WL + aoff + kk + 16 * WSTR * 2);
            LDSM4(Bh[0], Bh[1], Bh[2], Bh[3], sbase + OFF_XH + boff + kk);
            LDSM4(Bh[4], Bh[5], Bh[6], Bh[7], sbase + OFF_XH + boff + kk + 16 * WSTR * 2);
            LDSM4(Bl[0], Bl[1], Bl[2], Bl[3], sbase + OFF_XL + boff + kk);
            LDSM4(Bl[4], Bl[5], Bl[6], Bl[7], sbase + OFF_XL + boff + kk + 16 * WSTR * 2);
            #pragma unroll
            for (int i = 0; i < 2; i++) {
                #pragma unroll
                for (int j = 0; j < 4; j++) {
                    mma16816(acc[i][j], Ah[i], Bh + j * 2);
                    mma16816(acc[i][j], Al[i], Bh + j * 2);
                    mma16816(acc[i][j], Ah[i], Bl + j * 2);
                }
            }
        }
        __syncthreads();   // X reads done -> lnbuf overlay is safe to write

        // D -> lnbuf[out][px] (stride LNS)
        #pragma unroll
        for (int i = 0; i < 2; i++) {
            #pragma unroll
            for (int j = 0; j < 4; j++) {
                int px = n_base + j * 8 + (lane & 3) * 2;
                int o0 = m_base + i * 16 + (lane >> 2);
                *(float2*)&lnbuf[o0 * LNS + px]       = make_float2(acc[i][j][0], acc[i][j][1]);
                *(float2*)&lnbuf[(o0 + 8) * LNS + px] = make_float2(acc[i][j][2], acc[i][j][3]);
            }
        }
        __syncthreads();

        {   // LayerNorm: 1024 tasks = 64 px x 8 heads x {k,v}; 2 per thread
            int p = tid & 63, hh = (tid >> 6) & 7;
            #pragma unroll
            for (int part = 0; part < 2; part++) {
                int rbase = hh * 32 + part * 16;
                float t[16]; float s = 0.f;
                #pragma unroll
                for (int d = 0; d < 16; d++) { t[d] = lnbuf[(rbase + d) * LNS + p]; s += t[d]; }
                float m = s * (1.f / 16.f);
                float var = 0.f;
                #pragma unroll
                for (int d = 0; d < 16; d++) { float dv = t[d] - m; var += dv * dv; }
                float inv = rcp_approx(sqrt_approx(var * (1.f / 15.f)) + EPS);
                #pragma unroll
                for (int d = 0; d < 16; d++)
                    lnbuf[(rbase + d) * LNS + p] =
                        lw[rbase + d] * ((t[d] - m) * inv) + lb[rbase + d];
            }
        }
        __syncthreads();

        {   // kv outer product (f32x2), 32 px per warp
            const float* kr = &lnbuf[(ohead * 32 + odd) * LNS + ophalf];
            #pragma unroll
            for (int p = 0; p < 32; p += 2) {
                ull k2 = *(const ull*)&kr[p];
                #pragma unroll
                for (int t = 0; t < 8; t++) {
                    ull v2 = *(const ull*)&lnbuf[(ohead * 32 + 16 + oe0 + t) * LNS + ophalf + p];
                    kvacc[t] = fma2(k2, v2, kvacc[t]);
                }
            }
        }
    }

    #pragma unroll
    for (int t = 0; t < 8; t++) {
        float2 v = unpack2(kvacc[t]);
        atomicAdd(&g_kv[((b * HEADS + ohead) * HC + odd) * HC + oe0 + t], v.x + v.y);
    }
}

// ============================================================================
// Kernel B: fold attention -> M1[b] = o1_w @ (A + I); emit bf16 hi/lo images.
// grid (32 slices x 8 batches), 512 threads, 4 M1 rows per slice.
// ============================================================================
__global__ void build_mats_kernel(const float* __restrict__ qkv_w,
                                  const float* __restrict__ o1_w,
                                  const float* __restrict__ o2_w)
{
    extern __shared__ float smf[];
    float* kvs = smf;           // 2048
    float* As  = smf + 2048;    // [128][129]
    const int tid = threadIdx.x;
    const int slice = blockIdx.x;   // 0..31 -> 4 M1 rows each
    const int b     = blockIdx.y;

    for (int i = tid; i < HEADS * HC * HC; i += 512)
        kvs[i] = g_kv[b * HEADS * HC * HC + i] * (1.f / NPIX);
    __syncthreads();

    for (int idx = tid; idx < CHN * CHN; idx += 512) {
        int j = idx >> 7, c = idx & 127;
        int h = j >> 4, e = j & 15;
        float s = 0.f;
        #pragma unroll
        for (int d = 0; d < HC; d++)
            s += qkv_w[(h * 48 + d) * CHN + c] * kvs[(h * HC + d) * HC + e];
        As[j * 129 + c] = s;
    }
    __syncthreads();

    {   // M1 slice: rows [slice*4, slice*4+4); 512 threads cover 4*128 exactly
        int o = slice * 4 + (tid >> 7), c = tid & 127;
        float s = o1_w[o * CHN + c];   // identity term
        #pragma unroll 8
        for (int j = 0; j < CHN; j++)
            s += o1_w[o * CHN + j] * As[j * 129 + c];
        __nv_bfloat16 hi, lo;
        split_bf16(s, hi, lo);
        g_m1[b][0][o][c] = hi;
        g_m1[b][1][o][c] = lo;
    }
    if (b == 0) {
        int o = slice * 4 + (tid >> 7), c = tid & 127;
        __nv_bfloat16 hi, lo;
        split_bf16(o2_w[o * CHN + c], hi, lo);
        g_o2[0][o][c] = hi;
        g_o2[1][o][c] = lo;
    }
}

// ============================================================================
// Kernel C: out = gelu( o2 @ gelu( M1[b] @ x ) + x ), both GEMMs mma.sync.
// 512 threads = 16 warps: 4(M) x 4(N); warp tile 32 out x 16 px; chunk 64 px.
// X and U in separate regions; epilogue2 residual reconstructed from X smem.
// ============================================================================
__global__ void __launch_bounds__(512, 1) mlp_kernel(
    const float* __restrict__ x, float* __restrict__ out)
{
    extern __shared__ __align__(16) unsigned char sm[];
    const int OFF_M1H = 0;          // 34816
    const int OFF_M1L = 34816;
    const int OFF_O2H = 69632;
    const int OFF_O2L = 104448;     // weights end 139264
    const int OFF_XH  = 139264;     // 64*WSTR*2 = 17408
    const int OFF_XL  = 156672;     // X end 174080
    const int OFF_UH  = 174080;
    const int OFF_UL  = 191488;     // total 208896

    const u32 sbase = smem_u32(sm);
    const int tid = threadIdx.x;
    const int wid = tid >> 5, lane = tid & 31;
    const int b = blockIdx.y;
    const int n0 = blockIdx.x * (PXC * NCHC);

    {   // weight images -> smem: 4352 float4 each pair
        const float4* s1 = (const float4*)&g_m1[b][0][0][0];
        const float4* s2 = (const float4*)&g_o2[0][0][0];
        float4* d1 = (float4*)(sm + OFF_M1H);
        float4* d2 = (float4*)(sm + OFF_O2H);
        #pragma unroll
        for (int i = 0; i < 8; i++) {
            d1[tid + i * 512] = s1[tid + i * 512];
            d2[tid + i * 512] = s2[tid + i * 512];
        }
        if (tid < 256) {
            d1[tid + 4096] = s1[tid + 4096];
            d2[tid + 4096] = s2[tid + 4096];
        }
    }

    // warp mapping: 4(M) x 4(N), warp tile 32 out x 16 px
    const int wm = wid & 3, wn = wid >> 2;
    const int m_base = wm * 32, n_base = wn * 16;
    const u32 aoff = (u32)((m_base + (lane & 15)) * WSTR + (lane >> 4) * 8) * 2;
    const u32 boff = (u32)((n_base + (lane & 7) + (lane >> 4) * 8) * WSTR
                           + ((lane >> 3) & 1) * 8) * 2;

    // loader mapping: 2 adjacent channels x 8 px per thread
    const int lc2 = (tid & 63) * 2, lpx = (tid >> 6) * 8;
    const float* gx0 = x + ((size_t)b * CHN + lc2) * NPIX + lpx;
    const float* gx1 = gx0 + NPIX;

    // prefetch chunk 0
    float vv0[8], vv1[8];
    {
        const float4* g0 = (const float4*)(gx0 + n0);
        const float4* g1 = (const float4*)(gx1 + n0);
        float4 a0 = g0[0], a1 = g0[1], c0 = g1[0], c1 = g1[1];
        vv0[0]=a0.x; vv0[1]=a0.y; vv0[2]=a0.z; vv0[3]=a0.w;
        vv0[4]=a1.x; vv0[5]=a1.y; vv0[6]=a1.z; vv0[7]=a1.w;
        vv1[0]=c0.x; vv1[1]=c0.y; vv1[2]=c0.z; vv1[3]=c0.w;
        vv1[4]=c1.x; vv1[5]=c1.y; vv1[6]=c1.z; vv1[7]=c1.w;
    }

    for (int ch = 0; ch < NCHC; ch++) {
        const int nb = n0 + ch * PXC;
        {   // current chunk regs -> X split (packed 4B stores)
            #pragma unroll
            for (int j = 0; j < 8; j++) {
                u32 h2, l2;
                split_pair(vv0[j], vv1[j], h2, l2);
                int boffj = ((lpx + j) * WSTR + lc2) * 2;
                *(u32*)(sm + OFF_XH + boffj) = h2;
                *(u32*)(sm + OFF_XL + boffj) = l2;
            }
        }
        if (ch + 1 < NCHC) {   // prefetch next chunk
            const float4* g0 = (const float4*)(gx0 + n0 + (ch + 1) * PXC);
            const float4* g1 = (const float4*)(gx1 + n0 + (ch + 1) * PXC);
            float4 a0 = g0[0], a1 = g0[1], c0 = g1[0], c1 = g1[1];
            vv0[0]=a0.x; vv0[1]=a0.y; vv0[2]=a0.z; vv0[3]=a0.w;
            vv0[4]=a1.x; vv0[5]=a1.y; vv0[6]=a1.z; vv0[7]=a1.w;
            vv1[0]=c0.x; vv1[1]=c0.y; vv1[2]=c0.z; vv1[3]=c0.w;
            vv1[4]=c1.x; vv1[5]=c1.y; vv1[6]=c1.z; vv1[7]=c1.w;
        }
        __syncthreads();

        // ---- GEMM1: D1 = M1 @ x ----
        float a1c[2][2][4];
        #pragma unroll
        for (int i = 0; i < 2; i++)
            #pragma unroll
            for (int j = 0; j < 2; j++)
                #pragma unroll
                for (int q = 0; q < 4; q++) a1c[i][j][q] = 0.f;

        #pragma unroll
        for (int ks = 0; ks < 8; ks++) {
            const u32 kk = ks * 32;
            u32 Ah[2][4], Al[2][4], Bh[4], Bl[4];
            LDSM4(Ah[0][0], Ah[0][1], Ah[0][2], Ah[0][3], sbase + OFF_M1H + aoff + kk);
            LDSM4(Ah[1][0], Ah[1][1], Ah[1][2], Ah[1][3], sbase + OFF_M1H + aoff + kk + 16 * WSTR * 2);
            LDSM4(Al[0][0], Al[0][1], Al[0][2], Al[0][3], sbase + OFF_M1L + aoff + kk);
            LDSM4(Al[1][0], Al[1][1], Al[1][2], Al[1][3], sbase + OFF_M1L + aoff + kk + 16 * WSTR * 2);
            LDSM4(Bh[0], Bh[1], Bh[2], Bh[3], sbase + OFF_XH + boff + kk);
            LDSM4(Bl[0], Bl[1], Bl[2], Bl[3], sbase + OFF_XL + boff + kk);
            #pragma unroll
            for (int i = 0; i < 2; i++)
                #pragma unroll
                for (int j = 0; j < 2; j++) {
                    mma16816(a1c[i][j], Ah[i], Bh + j * 2);
                    mma16816(a1c[i][j], Al[i], Bh + j * 2);
                    mma16816(a1c[i][j], Ah[i], Bl + j * 2);
                }
        }

        {   // epilogue1: u = gelu(D1), split, store transposed [px][chan] -> U
            __nv_bfloat16* uh = (__nv_bfloat16*)(sm + OFF_UH);
            __nv_bfloat16* ul = (__nv_bfloat16*)(sm + OFF_UL);
            #pragma unroll
            for (int i = 0; i < 2; i++)
                #pragma unroll
                for (int j = 0; j < 2; j++) {
                    int px = n_base + j * 8 + (lane & 3) * 2;
                    int o0 = m_base + i * 16 + (lane >> 2);
                    #pragma unroll
                    for (int q = 0; q < 4; q++) {
                        int pp = px + (q & 1);
                        int oo = o0 + (q >> 1) * 8;
                        float u = gelu_fast(a1c[i][j][q]);
                        __nv_bfloat16 hi, lo;
                        split_bf16(u, hi, lo);
                        uh[pp * WSTR + oo] = hi;
                        ul[pp * WSTR + oo] = lo;
                    }
                }
        }
        __syncthreads();

        // ---- GEMM2: D2 = o2 @ u ----
        float a2c[2][2][4];
        #pragma unroll
        for (int i = 0; i < 2; i++)
            #pragma unroll
            for (int j = 0; j < 2; j++)
                #pragma unroll
                for (int q = 0; q < 4; q++) a2c[i][j][q] = 0.f;

        #pragma unroll
        for (int ks = 0; ks < 8; ks++) {
            const u32 kk = ks * 32;
            u32 Ah[2][4], Al[2][4], Bh[4], Bl[4];
            LDSM4(Ah[0][0], Ah[0][1], Ah[0][2], Ah[0][3], sbase + OFF_O2H + aoff + kk);
            LDSM4(Ah[1][0], Ah[1][1], Ah[1][2], Ah[1][3], sbase + OFF_O2H + aoff + kk + 16 * WSTR * 2);
            LDSM4(Al[0][0], Al[0][1], Al[0][2], Al[0][3], sbase + OFF_O2L + aoff + kk);
            LDSM4(Al[1][0], Al[1][1], Al[1][2], Al[1][3], sbase + OFF_O2L + aoff + kk + 16 * WSTR * 2);
            LDSM4(Bh[0], Bh[1], Bh[2], Bh[3], sbase + OFF_UH + boff + kk);
            LDSM4(Bl[0], Bl[1], Bl[2], Bl[3], sbase + OFF_UL + boff + kk);
            #pragma unroll
            for (int i = 0; i < 2; i++)
                #pragma unroll
                for (int j = 0; j < 2; j++) {
                    mma16816(a2c[i][j], Ah[i], Bh + j * 2);
                    mma16816(a2c[i][j], Al[i], Bh + j * 2);
                    mma16816(a2c[i][j], Ah[i], Bl + j * 2);
                }
        }

        {   // epilogue2: out = gelu(D2 + x); residual rebuilt from X smem (hi+lo)
            const __nv_bfloat16* xh = (const __nv_bfloat16*)(sm + OFF_XH);
            const __nv_bfloat16* xl = (const __nv_bfloat16*)(sm + OFF_XL);
            #pragma unroll
            for (int i = 0; i < 2; i++)
                #pragma unroll
                for (int j = 0; j < 2; j++) {
                    int pxl = n_base + j * 8 + (lane & 3) * 2;
                    int o0 = m_base + i * 16 + (lane >> 2);
                    #pragma unroll
                    for (int half = 0; half < 2; half++) {
                        int oo = o0 + half * 8;
                        u32 h0 = *(const u16*)&xh[pxl * WSTR + oo];
                        u32 l0 = *(const u16*)&xl[pxl * WSTR + oo];
                        u32 h1 = *(const u16*)&xh[(pxl + 1) * WSTR + oo];
                        u32 l1 = *(const u16*)&xl[(pxl + 1) * WSTR + oo];
                        float xv0 = __uint_as_float(h0 << 16) + __uint_as_float(l0 << 16);
                        float xv1 = __uint_as_float(h1 << 16) + __uint_as_float(l1 << 16);
                        float2 r;
                        r.x = gelu_fast(a2c[i][j][half * 2 + 0] + xv0);
                        r.y = gelu_fast(a2c[i][j][half * 2 + 1] + xv1);
                        *(float2*)(out + ((size_t)b * CHN + oo) * NPIX + nb + pxl) = r;
                    }
                }
        }
        __syncthreads();   // U reads (GEMM2) + X reads (E2) done before next chunk
    }
}

// ============================================================================
extern "C" void kernel_launch(void* const* d_in, const int* in_sizes, int n_in,
                              void* d_out, int out_size) {
    const float* x     = (const float*)d_in[0];
    const float* qkv_w = (const float*)d_in[1];
    const float* o1_w  = (const float*)d_in[2];
    const float* o2_w  = (const float*)d_in[3];
    const float* klw   = (const float*)d_in[4];
    const float* klb   = (const float*)d_in[5];
    const float* vlw   = (const float*)d_in[6];
    const float* vlb   = (const float*)d_in[7];
    float* out = (float*)d_out;

    const int SMEM_A = 208896;
    const int SMEM_B = (2048 + 128 * 129) * (int)sizeof(float);
    const int SMEM_C = 208896;

    cudaFuncSetAttribute(kv_accum_kernel,   cudaFuncAttributeMaxDynamicSharedMemorySize, SMEM_A);
    cudaFuncSetAttribute(build_mats_kernel, cudaFuncAttributeMaxDynamicSharedMemorySize, SMEM_B);
    cudaFuncSetAttribute(mlp_kernel,        cudaFuncAttributeMaxDynamicSharedMemorySize, SMEM_C);

    zero_kv_kernel<<<32, 512>>>();
    prep_wkv_kernel<<<64, 512>>>(qkv_w);
    kv_accum_kernel<<<dim3(NPIX / (PXA * NCHA), BATCH), 512, SMEM_A>>>(
        x, klw, klb, vlw, vlb);
    build_mats_kernel<<<dim3(32, BATCH), 512, SMEM_B>>>(qkv_w, o1_w, o2_w);
    mlp_kernel<<<dim3(NPIX / (PXC * NCHC), BATCH), 512, SMEM_C>>>(x, out);
}